// round 9
// baseline (speedup 1.0000x reference)
#include <cuda_runtime.h>
#include <cuda_bf16.h>
#include <math.h>
#include <stdint.h>

// ---------------- problem constants (fixed shapes) ----------------
#define BATCH   2
#define NATOM   2048
#define DATOM   128
#define NHEAD   4
#define DHEAD   32
#define DFF     512
#define DMODEL  512
#define NPAIR   16384
#define NTOK    512
#define ROWS    (BATCH*NATOM)      // 4096
#define MAXG    96                 // max atoms per token group (avg ~4; 96 astronomically safe)

// ---------------- static device scratch ----------------
__device__ float g_qkvg  [ROWS*4*DATOM];      // [Q|K|V|G] per row, stride 512
__device__ float g_attout[ROWS*DATOM];
__device__ float g_q1    [ROWS*DATOM];
__device__ float g_u     [ROWS*DFF];
__device__ float g_feat  [ROWS*DMODEL];
__device__ __align__(16) float g_biasc[(size_t)ROWS*MAXG*NHEAD];  // compact in-group bias
__device__ __align__(16) int   g_winc [(size_t)ROWS*MAXG];        // last-write-wins winner
__device__ int   g_gs[ROWS], g_ge[ROWS];
__device__ int   g_ts[BATCH*NTOK], g_tc[BATCH*NTOK];

// ---------------- helpers ----------------
__device__ __forceinline__ int d_lower_bound(const int* a, int n, int v) {
    int lo = 0, hi = n;
    while (lo < hi) { int m = (lo + hi) >> 1; if (a[m] < v) lo = m + 1; else hi = m; }
    return lo;
}
__device__ __forceinline__ int d_upper_bound(const int* a, int n, int v) {
    int lo = 0, hi = n;
    while (lo < hi) { int m = (lo + hi) >> 1; if (a[m] <= v) lo = m + 1; else hi = m; }
    return lo;
}
__device__ __forceinline__ float d_sigmoid(float x) { return 1.0f / (1.0f + __expf(-x)); }

__device__ __forceinline__ void mma_bf16(float d[4], const uint32_t a[4], const uint32_t b[2]) {
    asm volatile(
        "mma.sync.aligned.m16n8k16.row.col.f32.bf16.bf16.f32 "
        "{%0,%1,%2,%3}, {%4,%5,%6,%7}, {%8,%9}, {%0,%1,%2,%3};\n"
        : "+f"(d[0]), "+f"(d[1]), "+f"(d[2]), "+f"(d[3])
        : "r"(a[0]), "r"(a[1]), "r"(a[2]), "r"(a[3]), "r"(b[0]), "r"(b[1]));
}
__device__ __forceinline__ void cvt_hl(float x, unsigned short& h, unsigned short& l) {
    __nv_bfloat16 hb = __float2bfloat16(x);
    float r = x - __bfloat162float(hb);
    h = __bfloat16_as_ushort(hb);
    l = __bfloat16_as_ushort(__float2bfloat16(r));
}

// warp-fused LayerNorm of one 128-wide row held as float4 per lane (lane = col quad)
__device__ __forceinline__ void warp_ln4(float4& v, const float* __restrict__ g,
                                         const float* __restrict__ b, int lane) {
    float s  = v.x + v.y + v.z + v.w;
    float sq = v.x*v.x + v.y*v.y + v.z*v.z + v.w*v.w;
    #pragma unroll
    for (int o = 16; o; o >>= 1) {
        s  += __shfl_xor_sync(0xffffffffu, s,  o);
        sq += __shfl_xor_sync(0xffffffffu, sq, o);
    }
    float mean = s * (1.0f/DATOM);
    float var  = sq * (1.0f/DATOM) - mean*mean;
    float inv  = rsqrtf(var + 1e-5f);
    float4 gv = *(const float4*)(g + (lane<<2));
    float4 bv = *(const float4*)(b + (lane<<2));
    v.x = (v.x - mean)*inv*gv.x + bv.x;
    v.y = (v.y - mean)*inv*gv.y + bv.y;
    v.z = (v.z - mean)*inv*gv.z + bv.z;
    v.w = (v.w - mean)*inv*gv.w + bv.w;
}

// ============================================================================
// Split-bf16 tensor-core GEMM with FULL-K smem residency (dynamic smem).
// Block tile BM x 64. K processed in KTILES chunks of 128. One sync per chunk.
// LNA: apply row LayerNorm (lng/lnb) to A during load (requires lda==128, KTILES==1).
// EPI: 0 = store C; 1 = qkvg weight-select; 2 = wo gated-residual; 4 = w3 res-add
// ============================================================================
#define AST 136   // smem K-stride (bf16 elems)

template<int BM, int KTILES, int EPI, bool LNA>
__global__ __launch_bounds__(256) void k_mma(
    const float* __restrict__ A, int lda,
    const float* __restrict__ B0, const float* __restrict__ B1t,
    const float* __restrict__ B2t, const float* __restrict__ B3t,
    int ldb, float* __restrict__ C, int ldc, const float* __restrict__ aux,
    const float* __restrict__ lng, const float* __restrict__ lnb) {
    constexpr int WR  = (BM == 128) ? 4 : 2;
    constexpr int WTM = BM / WR;            // 32
    constexpr int WTN = 64 / (8 / WR);      // 32 (BM=128) or 16 (BM=64)
    constexpr int MT  = WTM / 16;           // 2
    constexpr int NT  = WTN / 8;            // 4 or 2

    extern __shared__ __align__(16) char smraw[];
    __nv_bfloat16* Ah = (__nv_bfloat16*)smraw;
    __nv_bfloat16* Al = Ah + BM*AST;
    __nv_bfloat16* Bh = Al + BM*AST;
    __nv_bfloat16* Bl = Bh + 64*AST;

    int tid = threadIdx.x, warp = tid >> 5, lane = tid & 31;
    int wm = warp % WR, wn = warp / WR;
    int gq = lane >> 2, t4 = lane & 3;
    int bm = blockIdx.y * BM;

    const float* Bsel; int bn;
    if (EPI == 1) {
        int wi = blockIdx.x >> 1;
        Bsel = (wi == 0) ? B0 : (wi == 1) ? B1t : (wi == 2) ? B2t : B3t;
        bn = (blockIdx.x & 1) * 64;
    } else { Bsel = B0; bn = blockIdx.x * 64; }
    int cn = blockIdx.x * 64;

    float acc[MT][NT][4] = {};

    for (int kt = 0; kt < KTILES; kt++) {
        // ---- load (+ optional fused LN) + split A tile: BM x 128 fp32 ----
        // each warp holds one full row per iteration: r = warp + 8*it, lane = col quad
        #pragma unroll
        for (int it = 0; it < BM/8; it++) {
            int idx = tid + it*256;
            int r = idx >> 5, c4 = (idx & 31) << 2;
            float4 v = *(const float4*)(A + (size_t)(bm + r) * lda + kt*128 + c4);
            if constexpr (LNA) warp_ln4(v, lng, lnb, lane);
            unsigned short h0,l0,h1,l1,h2,l2,h3,l3;
            cvt_hl(v.x,h0,l0); cvt_hl(v.y,h1,l1); cvt_hl(v.z,h2,l2); cvt_hl(v.w,h3,l3);
            *(uint32_t*)&Ah[r*AST + c4    ] = (uint32_t)h0 | ((uint32_t)h1 << 16);
            *(uint32_t*)&Ah[r*AST + c4 + 2] = (uint32_t)h2 | ((uint32_t)h3 << 16);
            *(uint32_t*)&Al[r*AST + c4    ] = (uint32_t)l0 | ((uint32_t)l1 << 16);
            *(uint32_t*)&Al[r*AST + c4 + 2] = (uint32_t)l2 | ((uint32_t)l3 << 16);
        }
        // ---- load + split B tile: 128(K) x 64(N) fp32, store K-major per col ----
        #pragma unroll
        for (int it = 0; it < 8; it++) {
            int idx = tid + it*256;
            int k = idx >> 4, n4 = (idx & 15) << 2;
            float4 v = *(const float4*)(Bsel + (size_t)(kt*128 + k) * ldb + bn + n4);
            float e[4] = {v.x, v.y, v.z, v.w};
            #pragma unroll
            for (int j = 0; j < 4; j++) {
                __nv_bfloat16 hb = __float2bfloat16(e[j]);
                Bh[(n4+j)*AST + k] = hb;
                Bl[(n4+j)*AST + k] = __float2bfloat16(e[j] - __bfloat162float(hb));
            }
        }
        __syncthreads();

        #pragma unroll
        for (int kk = 0; kk < 8; kk++) {
            int kb = kk * 16;
            uint32_t afh[MT][4], afl[MT][4], bfh[NT][2], bfl[NT][2];
            #pragma unroll
            for (int mt = 0; mt < MT; mt++) {
                int r0 = wm * WTM + mt * 16 + gq;
                afh[mt][0] = *(const uint32_t*)&Ah[ r0      *AST + kb + 2*t4    ];
                afh[mt][1] = *(const uint32_t*)&Ah[(r0 + 8) *AST + kb + 2*t4    ];
                afh[mt][2] = *(const uint32_t*)&Ah[ r0      *AST + kb + 2*t4 + 8];
                afh[mt][3] = *(const uint32_t*)&Ah[(r0 + 8) *AST + kb + 2*t4 + 8];
                afl[mt][0] = *(const uint32_t*)&Al[ r0      *AST + kb + 2*t4    ];
                afl[mt][1] = *(const uint32_t*)&Al[(r0 + 8) *AST + kb + 2*t4    ];
                afl[mt][2] = *(const uint32_t*)&Al[ r0      *AST + kb + 2*t4 + 8];
                afl[mt][3] = *(const uint32_t*)&Al[(r0 + 8) *AST + kb + 2*t4 + 8];
            }
            #pragma unroll
            for (int nt = 0; nt < NT; nt++) {
                int c0 = wn * WTN + nt * 8 + gq;
                bfh[nt][0] = *(const uint32_t*)&Bh[c0*AST + kb + 2*t4    ];
                bfh[nt][1] = *(const uint32_t*)&Bh[c0*AST + kb + 2*t4 + 8];
                bfl[nt][0] = *(const uint32_t*)&Bl[c0*AST + kb + 2*t4    ];
                bfl[nt][1] = *(const uint32_t*)&Bl[c0*AST + kb + 2*t4 + 8];
            }
            #pragma unroll
            for (int mt = 0; mt < MT; mt++)
                #pragma unroll
                for (int nt = 0; nt < NT; nt++) {
                    mma_bf16(acc[mt][nt], afh[mt], bfh[nt]);
                    mma_bf16(acc[mt][nt], afh[mt], bfl[nt]);
                    mma_bf16(acc[mt][nt], afl[mt], bfh[nt]);
                }
        }
        if (KTILES > 1) __syncthreads();
    }

    // ---- epilogue ----
    #pragma unroll
    for (int mt = 0; mt < MT; mt++)
        #pragma unroll
        for (int nt = 0; nt < NT; nt++)
            #pragma unroll
            for (int ci = 0; ci < 4; ci++) {
                int r = bm + wm * WTM + mt * 16 + gq + ((ci >> 1) ? 8 : 0);
                int c = cn + wn * WTN + nt * 8 + 2 * t4 + (ci & 1);
                float v = acc[mt][nt][ci];
                if constexpr (EPI == 0 || EPI == 1) {
                    C[(size_t)r * ldc + c] = v;
                } else if constexpr (EPI == 2) {
                    float gt = g_qkvg[(size_t)r * 512 + 3*DATOM + c];
                    g_q1[(size_t)r * DATOM + c] =
                        aux[(size_t)r * DATOM + c] + d_sigmoid(gt) * v;
                } else if constexpr (EPI == 4) {
                    g_q1[(size_t)r * DATOM + c] += v;
                }
            }
}

// ---------- dual-B FFN MMA with fused LN on A: g_u = silu(LN(q1)@w1)*(LN(q1)@w2) ----------
__global__ __launch_bounds__(256) void k_mma_ffn(
    const float* __restrict__ A,
    const float* __restrict__ W1, const float* __restrict__ W2,
    const float* __restrict__ lng, const float* __restrict__ lnb) {
    extern __shared__ __align__(16) char smraw[];
    __nv_bfloat16* Ah  = (__nv_bfloat16*)smraw;
    __nv_bfloat16* Al  = Ah  + 128*AST;
    __nv_bfloat16* B1h = Al  + 128*AST;
    __nv_bfloat16* B1l = B1h + 64*AST;
    __nv_bfloat16* B2h = B1l + 64*AST;
    __nv_bfloat16* B2l = B2h + 64*AST;

    int tid = threadIdx.x, warp = tid >> 5, lane = tid & 31;
    int wm = warp & 3, wn = warp >> 2;           // 4x2 warps, warptile 32x32
    int gq = lane >> 2, t4 = lane & 3;
    int bm = blockIdx.y * 128;
    int bn = blockIdx.x * 64;

    float au[2][4][4] = {}, avv[2][4][4] = {};

    // ---- load + fused-LN + split A (128x128) ----
    #pragma unroll
    for (int it = 0; it < 16; it++) {
        int idx = tid + it*256;
        int r = idx >> 5, c4 = (idx & 31) << 2;
        float4 v = *(const float4*)(A + (size_t)(bm + r) * 128 + c4);
        warp_ln4(v, lng, lnb, lane);
        unsigned short h0,l0,h1,l1,h2,l2,h3,l3;
        cvt_hl(v.x,h0,l0); cvt_hl(v.y,h1,l1); cvt_hl(v.z,h2,l2); cvt_hl(v.w,h3,l3);
        *(uint32_t*)&Ah[r*AST + c4    ] = (uint32_t)h0 | ((uint32_t)h1 << 16);
        *(uint32_t*)&Ah[r*AST + c4 + 2] = (uint32_t)h2 | ((uint32_t)h3 << 16);
        *(uint32_t*)&Al[r*AST + c4    ] = (uint32_t)l0 | ((uint32_t)l1 << 16);
        *(uint32_t*)&Al[r*AST + c4 + 2] = (uint32_t)l2 | ((uint32_t)l3 << 16);
    }
    // ---- load + split B1, B2 (128K x 64N) ----
    #pragma unroll
    for (int it = 0; it < 8; it++) {
        int idx = tid + it*256;
        int k = idx >> 4, n4 = (idx & 15) << 2;
        float4 v1 = *(const float4*)(W1 + (size_t)k * DFF + bn + n4);
        float4 v2 = *(const float4*)(W2 + (size_t)k * DFF + bn + n4);
        float e1[4] = {v1.x,v1.y,v1.z,v1.w}, e2[4] = {v2.x,v2.y,v2.z,v2.w};
        #pragma unroll
        for (int j = 0; j < 4; j++) {
            __nv_bfloat16 hb = __float2bfloat16(e1[j]);
            B1h[(n4+j)*AST + k] = hb;
            B1l[(n4+j)*AST + k] = __float2bfloat16(e1[j] - __bfloat162float(hb));
            __nv_bfloat16 hb2 = __float2bfloat16(e2[j]);
            B2h[(n4+j)*AST + k] = hb2;
            B2l[(n4+j)*AST + k] = __float2bfloat16(e2[j] - __bfloat162float(hb2));
        }
    }
    __syncthreads();

    #pragma unroll
    for (int kk = 0; kk < 8; kk++) {
        int kb = kk * 16;
        uint32_t afh[2][4], afl[2][4];
        #pragma unroll
        for (int mt = 0; mt < 2; mt++) {
            int r0 = wm * 32 + mt * 16 + gq;
            afh[mt][0] = *(const uint32_t*)&Ah[ r0     *AST + kb + 2*t4    ];
            afh[mt][1] = *(const uint32_t*)&Ah[(r0 + 8)*AST + kb + 2*t4    ];
            afh[mt][2] = *(const uint32_t*)&Ah[ r0     *AST + kb + 2*t4 + 8];
            afh[mt][3] = *(const uint32_t*)&Ah[(r0 + 8)*AST + kb + 2*t4 + 8];
            afl[mt][0] = *(const uint32_t*)&Al[ r0     *AST + kb + 2*t4    ];
            afl[mt][1] = *(const uint32_t*)&Al[(r0 + 8)*AST + kb + 2*t4    ];
            afl[mt][2] = *(const uint32_t*)&Al[ r0     *AST + kb + 2*t4 + 8];
            afl[mt][3] = *(const uint32_t*)&Al[(r0 + 8)*AST + kb + 2*t4 + 8];
        }
        #pragma unroll
        for (int nt = 0; nt < 4; nt++) {
            int c0 = wn * 32 + nt * 8 + gq;
            uint32_t b1f[2] = {*(const uint32_t*)&B1h[c0*AST + kb + 2*t4], *(const uint32_t*)&B1h[c0*AST + kb + 2*t4 + 8]};
            uint32_t b1g[2] = {*(const uint32_t*)&B1l[c0*AST + kb + 2*t4], *(const uint32_t*)&B1l[c0*AST + kb + 2*t4 + 8]};
            uint32_t b2f[2] = {*(const uint32_t*)&B2h[c0*AST + kb + 2*t4], *(const uint32_t*)&B2h[c0*AST + kb + 2*t4 + 8]};
            uint32_t b2g[2] = {*(const uint32_t*)&B2l[c0*AST + kb + 2*t4], *(const uint32_t*)&B2l[c0*AST + kb + 2*t4 + 8]};
            #pragma unroll
            for (int mt = 0; mt < 2; mt++) {
                mma_bf16(au [mt][nt], afh[mt], b1f);
                mma_bf16(au [mt][nt], afh[mt], b1g);
                mma_bf16(au [mt][nt], afl[mt], b1f);
                mma_bf16(avv[mt][nt], afh[mt], b2f);
                mma_bf16(avv[mt][nt], afh[mt], b2g);
                mma_bf16(avv[mt][nt], afl[mt], b2f);
            }
        }
    }
    #pragma unroll
    for (int mt = 0; mt < 2; mt++)
        #pragma unroll
        for (int nt = 0; nt < 4; nt++)
            #pragma unroll
            for (int ci = 0; ci < 4; ci++) {
                int r = bm + wm * 32 + mt * 16 + gq + ((ci >> 1) ? 8 : 0);
                int c = bn + wn * 32 + nt * 8 + 2 * t4 + (ci & 1);
                float uu = au[mt][nt][ci];
                g_u[(size_t)r * DFF + c] = (uu * d_sigmoid(uu)) * avv[mt][nt][ci];
            }
}

// ---------------- fused prep: group ranges + token ranges + winner zero ----------------
__global__ void k_prep(const int* __restrict__ tok) {
    int idx = blockIdx.x * blockDim.x + threadIdx.x;
    if (idx < ROWS*MAXG/4)
        ((int4*)g_winc)[idx] = make_int4(-1, -1, -1, -1);
    if (idx < ROWS) {
        int b = idx / NATOM, ii = idx % NATOM;
        const int* t = tok + b * NATOM;
        int v = t[ii];
        g_gs[idx] = d_lower_bound(t, NATOM, v);
        g_ge[idx] = d_upper_bound(t, NATOM, v);
    }
    if (idx < BATCH*NTOK) {
        int b = idx / NTOK, tt = idx % NTOK;
        const int* ta = tok + b * NATOM;
        int lo = d_lower_bound(ta, NATOM, tt);
        int hi = d_upper_bound(ta, NATOM, tt);
        g_ts[idx] = lo; g_tc[idx] = hi - lo;
    }
}

// ---------------- pair scatter pass 1: last-write-wins winner ----------------
__global__ void k_scatmax(const int* __restrict__ plmidx, const int* __restrict__ tok) {
    int gid = blockIdx.x * blockDim.x + threadIdx.x;
    if (gid >= BATCH * NPAIR) return;
    int b = gid / NPAIR, p = gid % NPAIR;
    int src = plmidx[(size_t)gid*2], dst = plmidx[(size_t)gid*2 + 1];
    if (tok[b*NATOM + src] != tok[b*NATOM + dst]) return;
    int i = b*NATOM + src;
    int slot = dst - g_gs[i];
    if (slot >= 0 && slot < MAXG)
        atomicMax(&g_winc[(size_t)i * MAXG + slot], p);
}

// ---------------- pass 2: slot-ordered bias fill (coalesced; zeros losers) ----------------
__global__ void k_biasfill(const float* __restrict__ p_lm,
                           const float* __restrict__ pb_w, const float* __restrict__ pb_b) {
    int slot = blockIdx.x * blockDim.x + threadIdx.x;
    if (slot >= ROWS * MAXG) return;
    int w = g_winc[slot];
    float4 v = make_float4(0.f, 0.f, 0.f, 0.f);
    if (w >= 0) {
        int i = slot / MAXG;
        int b = i / NATOM;
        const float* pl = p_lm + ((size_t)b * NPAIR + w) * 16;
        float h0 = pb_b[0], h1 = pb_b[1], h2 = pb_b[2], h3 = pb_b[3];
        #pragma unroll
        for (int k = 0; k < 16; k++) {
            float plk = pl[k];
            h0 += plk * pb_w[k*NHEAD + 0];
            h1 += plk * pb_w[k*NHEAD + 1];
            h2 += plk * pb_w[k*NHEAD + 2];
            h3 += plk * pb_w[k*NHEAD + 3];
        }
        v = make_float4(h0, h1, h2, h3);
    }
    ((float4*)g_biasc)[slot] = v;
}

// ---------------- block-diagonal attention: 1 block/atom, 1 warp/head ----------------
__global__ void k_attn() {
    int i = blockIdx.x;
    int b = i / NATOM;
    int h = threadIdx.x >> 5, lane = threadIdx.x & 31;
    int s = g_gs[i], e = g_ge[i];
    const float* qrow = g_qkvg + (size_t)i * 512;
    float qd = qrow[h*DHEAD + lane];
    const float* biasrow = g_biasc + (size_t)i * MAXG * NHEAD + h;
    float m = -1e30f, l = 0.0f, acc = 0.0f;
    for (int j = s; j < e; j++) {
        const float* row = g_qkvg + (size_t)(b*NATOM + j) * 512;
        float sc = qd * row[DATOM + h*DHEAD + lane];
        #pragma unroll
        for (int o = 16; o; o >>= 1) sc += __shfl_xor_sync(0xffffffffu, sc, o);
        int slot = j - s;
        float bias = (slot < MAXG) ? biasrow[(size_t)slot * NHEAD] : 0.0f;
        sc = sc * 0.17677669529663687f + bias;
        float mn = fmaxf(m, sc);
        float corr = __expf(m - mn);
        float w = __expf(sc - mn);
        l = l * corr + w;
        acc = acc * corr + w * row[2*DATOM + h*DHEAD + lane];
        m = mn;
    }
    g_attout[(size_t)i * DATOM + h*DHEAD + lane] = acc / l;
}

// ---------------- segment mean ----------------
__global__ void k_segmean(const float* __restrict__ tok_b, float* __restrict__ out) {
    int seg = blockIdx.x;
    int b = seg / NTOK;
    int d = threadIdx.x;
    int s = g_ts[seg], c = g_tc[seg];
    float sum = 0.0f;
    for (int k = 0; k < c; k++)
        sum += g_feat[(size_t)(b*NATOM + s + k) * DMODEL + d];
    out[(size_t)seg * DMODEL + d] = c ? (sum / (float)c + tok_b[d]) : 0.0f;
}

// ---------------- launch ----------------
extern "C" void kernel_launch(void* const* d_in, const int* in_sizes, int n_in,
                              void* d_out, int out_size) {
    int shift = (in_sizes[4] == 1) ? 1 : 0;
    const float* c_atom    = (const float*)d_in[0];
    const float* p_lm      = (const float*)d_in[1];
    const int*   p_lm_idx  = (const int*)  d_in[2];
    const int*   token_idx = (const int*)  d_in[3];
    const float* ln_attn_g = (const float*)d_in[4+shift];
    const float* ln_attn_b = (const float*)d_in[5+shift];
    const float* w_q       = (const float*)d_in[6+shift];
    const float* w_k       = (const float*)d_in[7+shift];
    const float* w_v       = (const float*)d_in[8+shift];
    const float* w_g       = (const float*)d_in[9+shift];
    const float* w_o       = (const float*)d_in[10+shift];
    const float* pb_w      = (const float*)d_in[11+shift];
    const float* pb_b      = (const float*)d_in[12+shift];
    const float* ln_ff_g   = (const float*)d_in[13+shift];
    const float* ln_ff_b   = (const float*)d_in[14+shift];
    const float* sw_w1     = (const float*)d_in[15+shift];
    const float* sw_w2     = (const float*)d_in[16+shift];
    const float* sw_w3     = (const float*)d_in[17+shift];
    const float* tok_w     = (const float*)d_in[18+shift];
    const float* tok_b     = (const float*)d_in[19+shift];
    float* out = (float*)d_out;

    float *p_qkvg, *p_attout, *p_q1, *p_u, *p_feat;
    cudaGetSymbolAddress((void**)&p_qkvg,   g_qkvg);
    cudaGetSymbolAddress((void**)&p_attout, g_attout);
    cudaGetSymbolAddress((void**)&p_q1,     g_q1);
    cudaGetSymbolAddress((void**)&p_u,      g_u);
    cudaGetSymbolAddress((void**)&p_feat,   g_feat);

    // dynamic smem opt-in (idempotent)
    const int SM128 = 2 * AST * (128 + 64) * 2;   // 104448 B
    const int SM64  = 2 * AST * ( 64 + 64) * 2;   //  69632 B
    const int SMFFN = 2 * AST * (128 + 128) * 2;  // 139264 B
    cudaFuncSetAttribute(k_mma<128,1,1,true >, cudaFuncAttributeMaxDynamicSharedMemorySize, SM128);
    cudaFuncSetAttribute(k_mma<128,1,0,false>, cudaFuncAttributeMaxDynamicSharedMemorySize, SM128);
    cudaFuncSetAttribute(k_mma<64,1,2,false>,  cudaFuncAttributeMaxDynamicSharedMemorySize, SM64);
    cudaFuncSetAttribute(k_mma<64,4,4,false>,  cudaFuncAttributeMaxDynamicSharedMemorySize, SM64);
    cudaFuncSetAttribute(k_mma_ffn,            cudaFuncAttributeMaxDynamicSharedMemorySize, SMFFN);

    // side stream for the bias chain (created once; same work every call)
    static cudaStream_t s_side = nullptr;
    static cudaEvent_t  e_fork = nullptr, e_join = nullptr;
    if (!s_side) {
        cudaStreamCreateWithFlags(&s_side, cudaStreamNonBlocking);
        cudaEventCreateWithFlags(&e_fork, cudaEventDisableTiming);
        cudaEventCreateWithFlags(&e_join, cudaEventDisableTiming);
    }

    // ---- fork: bias chain on side stream, overlapped with QKVG GEMM ----
    cudaEventRecord(e_fork, 0);
    cudaStreamWaitEvent(s_side, e_fork, 0);
    k_prep    <<<ROWS*MAXG/4/256, 256, 0, s_side>>>(token_idx);
    k_scatmax <<<(BATCH*NPAIR)/256, 256, 0, s_side>>>(p_lm_idx, token_idx);
    k_biasfill<<<ROWS*MAXG/256, 256, 0, s_side>>>(p_lm, pb_w, pb_b);
    cudaEventRecord(e_join, s_side);

    // ---- main chain (LN fused into GEMM A-loads) ----
    k_mma<128,1,1,true><<<dim3(8, ROWS/128), 256, SM128>>>(
        c_atom, 128, w_q, w_k, w_v, w_g, 128, p_qkvg, 512, nullptr, ln_attn_g, ln_attn_b);

    cudaStreamWaitEvent(0, e_join, 0);
    k_attn<<<ROWS, 128>>>();

    k_mma<64,1,2,false><<<dim3(2, ROWS/64), 256, SM64>>>(
        p_attout, 128, w_o, w_o, w_o, w_o, 128, nullptr, 0, c_atom, nullptr, nullptr);
    k_mma_ffn<<<dim3(DFF/64, ROWS/128), 256, SMFFN>>>(p_q1, sw_w1, sw_w2, ln_ff_g, ln_ff_b);
    k_mma<64,4,4,false><<<dim3(2, ROWS/64), 256, SM64>>>(
        p_u, 512, sw_w3, sw_w3, sw_w3, sw_w3, 128, nullptr, 0, nullptr, nullptr, nullptr);
    k_mma<128,1,0,false><<<dim3(DMODEL/64, ROWS/128), 256, SM128>>>(
        p_q1, 128, tok_w, tok_w, tok_w, tok_w, 512, p_feat, 512, nullptr, nullptr, nullptr);
    k_segmean<<<BATCH*NTOK, DMODEL>>>(tok_b, out);
}

// round 12
// speedup vs baseline: 1.4778x; 1.4778x over previous
#include <cuda_runtime.h>
#include <cuda_bf16.h>
#include <math.h>
#include <stdint.h>

// ---------------- problem constants (fixed shapes) ----------------
#define BATCH   2
#define NATOM   2048
#define DATOM   128
#define NHEAD   4
#define DHEAD   32
#define DFF     512
#define DMODEL  512
#define NPAIR   16384
#define NTOK    512
#define ROWS    (BATCH*NATOM)      // 4096
#define MAXG    96                 // max atoms per token group (avg ~4; 96 astronomically safe)

// ---------------- static device scratch ----------------
__device__ float g_qn    [ROWS*DATOM];
__device__ float g_qkvg  [ROWS*4*DATOM];      // [Q|K|V|G] per row, stride 512
__device__ float g_attout[ROWS*DATOM];
__device__ float g_q1    [ROWS*DATOM];
__device__ float g_h     [ROWS*DATOM];
__device__ float g_u     [ROWS*DFF];
__device__ float g_feat  [ROWS*DMODEL];
__device__ __align__(16) float g_biasc[(size_t)ROWS*MAXG*NHEAD];  // compact in-group bias
__device__ __align__(16) int   g_winc [(size_t)ROWS*MAXG];        // last-write-wins winner
__device__ int   g_gs[ROWS], g_ge[ROWS];
__device__ int   g_ts[BATCH*NTOK], g_tc[BATCH*NTOK];

// ---------------- helpers ----------------
__device__ __forceinline__ int d_lower_bound(const int* a, int n, int v) {
    int lo = 0, hi = n;
    while (lo < hi) { int m = (lo + hi) >> 1; if (a[m] < v) lo = m + 1; else hi = m; }
    return lo;
}
__device__ __forceinline__ int d_upper_bound(const int* a, int n, int v) {
    int lo = 0, hi = n;
    while (lo < hi) { int m = (lo + hi) >> 1; if (a[m] <= v) lo = m + 1; else hi = m; }
    return lo;
}
__device__ __forceinline__ float d_sigmoid(float x) { return 1.0f / (1.0f + __expf(-x)); }

__device__ __forceinline__ void mma_bf16(float d[4], const uint32_t a[4], const uint32_t b[2]) {
    asm volatile(
        "mma.sync.aligned.m16n8k16.row.col.f32.bf16.bf16.f32 "
        "{%0,%1,%2,%3}, {%4,%5,%6,%7}, {%8,%9}, {%0,%1,%2,%3};\n"
        : "+f"(d[0]), "+f"(d[1]), "+f"(d[2]), "+f"(d[3])
        : "r"(a[0]), "r"(a[1]), "r"(a[2]), "r"(a[3]), "r"(b[0]), "r"(b[1]));
}
__device__ __forceinline__ void ldsm_x4(uint32_t& d0, uint32_t& d1, uint32_t& d2, uint32_t& d3,
                                        uint32_t saddr) {
    asm volatile("ldmatrix.sync.aligned.m8n8.x4.shared.b16 {%0,%1,%2,%3}, [%4];"
                 : "=r"(d0), "=r"(d1), "=r"(d2), "=r"(d3) : "r"(saddr));
}
__device__ __forceinline__ void cvt_hl(float x, unsigned short& h, unsigned short& l) {
    __nv_bfloat16 hb = __float2bfloat16(x);
    float r = x - __bfloat162float(hb);
    h = __bfloat16_as_ushort(hb);
    l = __bfloat16_as_ushort(__float2bfloat16(r));
}

// ---------------- LayerNorm: one warp per row of 128 ----------------
__global__ void k_ln(const float* __restrict__ x, const float* __restrict__ g,
                     const float* __restrict__ b, float* __restrict__ y) {
    int warp = (blockIdx.x * blockDim.x + threadIdx.x) >> 5;
    int lane = threadIdx.x & 31;
    if (warp >= ROWS) return;
    const float* xr = x + (size_t)warp * DATOM;
    float v0 = xr[lane], v1 = xr[lane+32], v2 = xr[lane+64], v3 = xr[lane+96];
    float s  = v0+v1+v2+v3;
    float sq = v0*v0+v1*v1+v2*v2+v3*v3;
    #pragma unroll
    for (int o = 16; o; o >>= 1) {
        s  += __shfl_xor_sync(0xffffffffu, s,  o);
        sq += __shfl_xor_sync(0xffffffffu, sq, o);
    }
    float mean = s * (1.0f/DATOM);
    float var  = sq * (1.0f/DATOM) - mean*mean;
    float inv  = rsqrtf(var + 1e-5f);
    float* yr = y + (size_t)warp * DATOM;
    yr[lane]    = (v0-mean)*inv*g[lane]    + b[lane];
    yr[lane+32] = (v1-mean)*inv*g[lane+32] + b[lane+32];
    yr[lane+64] = (v2-mean)*inv*g[lane+64] + b[lane+64];
    yr[lane+96] = (v3-mean)*inv*g[lane+96] + b[lane+96];
}

// ============================================================================
// Split-bf16 tensor-core GEMM, full-K smem residency, ldmatrix fragment loads.
// Block tile BM x 64. K in KTILES chunks of 128. One sync per chunk.
// EPI: 0 = store C; 1 = qkvg weight-select; 2 = wo gated-residual; 4 = w3 res-add
// ============================================================================
#define AST 136   // smem K-stride (bf16 elems); LDSM rows at 68-word stride -> conflict-free

template<int BM, int KTILES, int EPI>
__global__ __launch_bounds__(256) void k_mma(
    const float* __restrict__ A, int lda,
    const float* __restrict__ B0, const float* __restrict__ B1t,
    const float* __restrict__ B2t, const float* __restrict__ B3t,
    int ldb, float* __restrict__ C, int ldc, const float* __restrict__ aux) {
    constexpr int WR  = (BM == 128) ? 4 : 2;
    constexpr int WTM = BM / WR;            // 32
    constexpr int WTN = 64 / (8 / WR);      // 32 (BM=128) or 16 (BM=64)
    constexpr int MT  = WTM / 16;           // 2
    constexpr int NT  = WTN / 8;            // 4 or 2

    extern __shared__ __align__(16) char smraw[];
    __nv_bfloat16* Ah = (__nv_bfloat16*)smraw;
    __nv_bfloat16* Al = Ah + BM*AST;
    __nv_bfloat16* Bh = Al + BM*AST;
    __nv_bfloat16* Bl = Bh + 64*AST;

    int tid = threadIdx.x, warp = tid >> 5, lane = tid & 31;
    int wm = warp % WR, wn = warp / WR;
    int gq = lane >> 2, t4 = lane & 3;
    int bm = blockIdx.y * BM;

    const float* Bsel; int bn;
    if (EPI == 1) {
        int wi = blockIdx.x >> 1;
        Bsel = (wi == 0) ? B0 : (wi == 1) ? B1t : (wi == 2) ? B2t : B3t;
        bn = (blockIdx.x & 1) * 64;
    } else { Bsel = B0; bn = blockIdx.x * 64; }
    int cn = blockIdx.x * 64;

    // ldmatrix per-lane address components
    uint32_t aBaseH = (uint32_t)__cvta_generic_to_shared(Ah);
    uint32_t aBaseL = (uint32_t)__cvta_generic_to_shared(Al);
    uint32_t bBaseH = (uint32_t)__cvta_generic_to_shared(Bh);
    uint32_t bBaseL = (uint32_t)__cvta_generic_to_shared(Bl);
    // A x4: lane l -> row wm*WTM + mt*16 + ((l>>3)&1)*8 + (l&7), col kb + (l>>4)*8
    int rA = wm*WTM + ((lane>>3)&1)*8 + (lane&7);
    int cA = (lane>>4)*8;
    // B x4 (two n-tiles per load): m=l>>3; row wn*WTN + ntp*16 + (m>>1)*8 + (l&7), col kb + (m&1)*8
    int rB = wn*WTN + ((lane>>4)<<3) + (lane&7);
    int cB = ((lane>>3)&1)*8;

    float acc[MT][NT][4] = {};

    for (int kt = 0; kt < KTILES; kt++) {
        // ---- load + split A tile: BM x 128 fp32 ----
        #pragma unroll
        for (int it = 0; it < BM/8; it++) {
            int idx = tid + it*256;
            int r = idx >> 5, c4 = (idx & 31) << 2;
            float4 v = *(const float4*)(A + (size_t)(bm + r) * lda + kt*128 + c4);
            unsigned short h0,l0,h1,l1,h2,l2,h3,l3;
            cvt_hl(v.x,h0,l0); cvt_hl(v.y,h1,l1); cvt_hl(v.z,h2,l2); cvt_hl(v.w,h3,l3);
            *(uint32_t*)&Ah[r*AST + c4    ] = (uint32_t)h0 | ((uint32_t)h1 << 16);
            *(uint32_t*)&Ah[r*AST + c4 + 2] = (uint32_t)h2 | ((uint32_t)h3 << 16);
            *(uint32_t*)&Al[r*AST + c4    ] = (uint32_t)l0 | ((uint32_t)l1 << 16);
            *(uint32_t*)&Al[r*AST + c4 + 2] = (uint32_t)l2 | ((uint32_t)l3 << 16);
        }
        // ---- load + split B tile: 128(K) x 64(N) fp32, store K-major per col ----
        #pragma unroll
        for (int it = 0; it < 8; it++) {
            int idx = tid + it*256;
            int k = idx >> 4, n4 = (idx & 15) << 2;
            float4 v = *(const float4*)(Bsel + (size_t)(kt*128 + k) * ldb + bn + n4);
            float e[4] = {v.x, v.y, v.z, v.w};
            #pragma unroll
            for (int j = 0; j < 4; j++) {
                __nv_bfloat16 hb = __float2bfloat16(e[j]);
                Bh[(n4+j)*AST + k] = hb;
                Bl[(n4+j)*AST + k] = __float2bfloat16(e[j] - __bfloat162float(hb));
            }
        }
        __syncthreads();

        #pragma unroll
        for (int kk = 0; kk < 8; kk++) {
            int kb = kk * 16;
            uint32_t afh[MT][4], afl[MT][4], bfh[NT][2], bfl[NT][2];
            #pragma unroll
            for (int mt = 0; mt < MT; mt++) {
                uint32_t off = (uint32_t)(((rA + mt*16)*AST + kb + cA) * 2);
                ldsm_x4(afh[mt][0], afh[mt][1], afh[mt][2], afh[mt][3], aBaseH + off);
                ldsm_x4(afl[mt][0], afl[mt][1], afl[mt][2], afl[mt][3], aBaseL + off);
            }
            #pragma unroll
            for (int ntp = 0; ntp < NT/2; ntp++) {
                uint32_t off = (uint32_t)(((rB + ntp*16)*AST + kb + cB) * 2);
                ldsm_x4(bfh[2*ntp][0], bfh[2*ntp][1], bfh[2*ntp+1][0], bfh[2*ntp+1][1], bBaseH + off);
                ldsm_x4(bfl[2*ntp][0], bfl[2*ntp][1], bfl[2*ntp+1][0], bfl[2*ntp+1][1], bBaseL + off);
            }
            #pragma unroll
            for (int mt = 0; mt < MT; mt++)
                #pragma unroll
                for (int nt = 0; nt < NT; nt++) {
                    mma_bf16(acc[mt][nt], afh[mt], bfh[nt]);
                    mma_bf16(acc[mt][nt], afh[mt], bfl[nt]);
                    mma_bf16(acc[mt][nt], afl[mt], bfh[nt]);
                }
        }
        if (KTILES > 1) __syncthreads();
    }

    // ---- epilogue ----
    #pragma unroll
    for (int mt = 0; mt < MT; mt++)
        #pragma unroll
        for (int nt = 0; nt < NT; nt++)
            #pragma unroll
            for (int ci = 0; ci < 4; ci++) {
                int r = bm + wm * WTM + mt * 16 + gq + ((ci >> 1) ? 8 : 0);
                int c = cn + wn * WTN + nt * 8 + 2 * t4 + (ci & 1);
                float v = acc[mt][nt][ci];
                if constexpr (EPI == 0 || EPI == 1) {
                    C[(size_t)r * ldc + c] = v;
                } else if constexpr (EPI == 2) {
                    float gt = g_qkvg[(size_t)r * 512 + 3*DATOM + c];
                    g_q1[(size_t)r * DATOM + c] =
                        aux[(size_t)r * DATOM + c] + d_sigmoid(gt) * v;
                } else if constexpr (EPI == 4) {
                    g_q1[(size_t)r * DATOM + c] += v;
                }
            }
}

// ---------- dual-B FFN MMA: g_u = silu(h@w1) * (h@w2), BM=128, K=128, ldmatrix ----------
__global__ __launch_bounds__(256) void k_mma_ffn(
    const float* __restrict__ A,
    const float* __restrict__ W1, const float* __restrict__ W2) {
    extern __shared__ __align__(16) char smraw[];
    __nv_bfloat16* Ah  = (__nv_bfloat16*)smraw;
    __nv_bfloat16* Al  = Ah  + 128*AST;
    __nv_bfloat16* B1h = Al  + 128*AST;
    __nv_bfloat16* B1l = B1h + 64*AST;
    __nv_bfloat16* B2h = B1l + 64*AST;
    __nv_bfloat16* B2l = B2h + 64*AST;

    int tid = threadIdx.x, warp = tid >> 5, lane = tid & 31;
    int wm = warp & 3, wn = warp >> 2;           // 4x2 warps, warptile 32x32
    int gq = lane >> 2, t4 = lane & 3;
    int bm = blockIdx.y * 128;
    int bn = blockIdx.x * 64;

    uint32_t aBaseH  = (uint32_t)__cvta_generic_to_shared(Ah);
    uint32_t aBaseL  = (uint32_t)__cvta_generic_to_shared(Al);
    uint32_t b1BaseH = (uint32_t)__cvta_generic_to_shared(B1h);
    uint32_t b1BaseL = (uint32_t)__cvta_generic_to_shared(B1l);
    uint32_t b2BaseH = (uint32_t)__cvta_generic_to_shared(B2h);
    uint32_t b2BaseL = (uint32_t)__cvta_generic_to_shared(B2l);
    int rA = wm*32 + ((lane>>3)&1)*8 + (lane&7);
    int cA = (lane>>4)*8;
    int rB = wn*32 + ((lane>>4)<<3) + (lane&7);
    int cB = ((lane>>3)&1)*8;

    float au[2][4][4] = {}, avv[2][4][4] = {};

    // ---- load + split A (128x128) ----
    #pragma unroll
    for (int it = 0; it < 16; it++) {
        int idx = tid + it*256;
        int r = idx >> 5, c4 = (idx & 31) << 2;
        float4 v = *(const float4*)(A + (size_t)(bm + r) * 128 + c4);
        unsigned short h0,l0,h1,l1,h2,l2,h3,l3;
        cvt_hl(v.x,h0,l0); cvt_hl(v.y,h1,l1); cvt_hl(v.z,h2,l2); cvt_hl(v.w,h3,l3);
        *(uint32_t*)&Ah[r*AST + c4    ] = (uint32_t)h0 | ((uint32_t)h1 << 16);
        *(uint32_t*)&Ah[r*AST + c4 + 2] = (uint32_t)h2 | ((uint32_t)h3 << 16);
        *(uint32_t*)&Al[r*AST + c4    ] = (uint32_t)l0 | ((uint32_t)l1 << 16);
        *(uint32_t*)&Al[r*AST + c4 + 2] = (uint32_t)l2 | ((uint32_t)l3 << 16);
    }
    // ---- load + split B1, B2 (128K x 64N) ----
    #pragma unroll
    for (int it = 0; it < 8; it++) {
        int idx = tid + it*256;
        int k = idx >> 4, n4 = (idx & 15) << 2;
        float4 v1 = *(const float4*)(W1 + (size_t)k * DFF + bn + n4);
        float4 v2 = *(const float4*)(W2 + (size_t)k * DFF + bn + n4);
        float e1[4] = {v1.x,v1.y,v1.z,v1.w}, e2[4] = {v2.x,v2.y,v2.z,v2.w};
        #pragma unroll
        for (int j = 0; j < 4; j++) {
            __nv_bfloat16 hb = __float2bfloat16(e1[j]);
            B1h[(n4+j)*AST + k] = hb;
            B1l[(n4+j)*AST + k] = __float2bfloat16(e1[j] - __bfloat162float(hb));
            __nv_bfloat16 hb2 = __float2bfloat16(e2[j]);
            B2h[(n4+j)*AST + k] = hb2;
            B2l[(n4+j)*AST + k] = __float2bfloat16(e2[j] - __bfloat162float(hb2));
        }
    }
    __syncthreads();

    #pragma unroll
    for (int kk = 0; kk < 8; kk++) {
        int kb = kk * 16;
        uint32_t afh[2][4], afl[2][4];
        uint32_t b1f[4][2], b1g[4][2], b2f[4][2], b2g[4][2];
        #pragma unroll
        for (int mt = 0; mt < 2; mt++) {
            uint32_t off = (uint32_t)(((rA + mt*16)*AST + kb + cA) * 2);
            ldsm_x4(afh[mt][0], afh[mt][1], afh[mt][2], afh[mt][3], aBaseH + off);
            ldsm_x4(afl[mt][0], afl[mt][1], afl[mt][2], afl[mt][3], aBaseL + off);
        }
        #pragma unroll
        for (int ntp = 0; ntp < 2; ntp++) {
            uint32_t off = (uint32_t)(((rB + ntp*16)*AST + kb + cB) * 2);
            ldsm_x4(b1f[2*ntp][0], b1f[2*ntp][1], b1f[2*ntp+1][0], b1f[2*ntp+1][1], b1BaseH + off);
            ldsm_x4(b1g[2*ntp][0], b1g[2*ntp][1], b1g[2*ntp+1][0], b1g[2*ntp+1][1], b1BaseL + off);
            ldsm_x4(b2f[2*ntp][0], b2f[2*ntp][1], b2f[2*ntp+1][0], b2f[2*ntp+1][1], b2BaseH + off);
            ldsm_x4(b2g[2*ntp][0], b2g[2*ntp][1], b2g[2*ntp+1][0], b2g[2*ntp+1][1], b2BaseL + off);
        }
        #pragma unroll
        for (int nt = 0; nt < 4; nt++)
            #pragma unroll
            for (int mt = 0; mt < 2; mt++) {
                mma_bf16(au [mt][nt], afh[mt], b1f[nt]);
                mma_bf16(au [mt][nt], afh[mt], b1g[nt]);
                mma_bf16(au [mt][nt], afl[mt], b1f[nt]);
                mma_bf16(avv[mt][nt], afh[mt], b2f[nt]);
                mma_bf16(avv[mt][nt], afh[mt], b2g[nt]);
                mma_bf16(avv[mt][nt], afl[mt], b2f[nt]);
            }
    }
    #pragma unroll
    for (int mt = 0; mt < 2; mt++)
        #pragma unroll
        for (int nt = 0; nt < 4; nt++)
            #pragma unroll
            for (int ci = 0; ci < 4; ci++) {
                int r = bm + wm * 32 + mt * 16 + gq + ((ci >> 1) ? 8 : 0);
                int c = bn + wn * 32 + nt * 8 + 2 * t4 + (ci & 1);
                float uu = au[mt][nt][ci];
                g_u[(size_t)r * DFF + c] = (uu * d_sigmoid(uu)) * avv[mt][nt][ci];
            }
}

// ---------------- fused prep: group ranges + token ranges + winner zero ----------------
__global__ void k_prep(const int* __restrict__ tok) {
    int idx = blockIdx.x * blockDim.x + threadIdx.x;
    if (idx < ROWS*MAXG/4)
        ((int4*)g_winc)[idx] = make_int4(-1, -1, -1, -1);
    if (idx < ROWS) {
        int b = idx / NATOM, ii = idx % NATOM;
        const int* t = tok + b * NATOM;
        int v = t[ii];
        g_gs[idx] = d_lower_bound(t, NATOM, v);
        g_ge[idx] = d_upper_bound(t, NATOM, v);
    }
    if (idx < BATCH*NTOK) {
        int b = idx / NTOK, tt = idx % NTOK;
        const int* ta = tok + b * NATOM;
        int lo = d_lower_bound(ta, NATOM, tt);
        int hi = d_upper_bound(ta, NATOM, tt);
        g_ts[idx] = lo; g_tc[idx] = hi - lo;
    }
}

// ---------------- pair scatter pass 1: last-write-wins winner ----------------
__global__ void k_scatmax(const int* __restrict__ plmidx, const int* __restrict__ tok) {
    int gid = blockIdx.x * blockDim.x + threadIdx.x;
    if (gid >= BATCH * NPAIR) return;
    int b = gid / NPAIR, p = gid % NPAIR;
    int src = plmidx[(size_t)gid*2], dst = plmidx[(size_t)gid*2 + 1];
    if (tok[b*NATOM + src] != tok[b*NATOM + dst]) return;
    int i = b*NATOM + src;
    int slot = dst - g_gs[i];
    if (slot >= 0 && slot < MAXG)
        atomicMax(&g_winc[(size_t)i * MAXG + slot], p);
}

// ---------------- pass 2: slot-ordered bias fill (coalesced; zeros losers) ----------------
__global__ void k_biasfill(const float* __restrict__ p_lm,
                           const float* __restrict__ pb_w, const float* __restrict__ pb_b) {
    int slot = blockIdx.x * blockDim.x + threadIdx.x;
    if (slot >= ROWS * MAXG) return;
    int w = g_winc[slot];
    float4 v = make_float4(0.f, 0.f, 0.f, 0.f);
    if (w >= 0) {
        int i = slot / MAXG;
        int b = i / NATOM;
        const float* pl = p_lm + ((size_t)b * NPAIR + w) * 16;
        float h0 = pb_b[0], h1 = pb_b[1], h2 = pb_b[2], h3 = pb_b[3];
        #pragma unroll
        for (int k = 0; k < 16; k++) {
            float plk = pl[k];
            h0 += plk * pb_w[k*NHEAD + 0];
            h1 += plk * pb_w[k*NHEAD + 1];
            h2 += plk * pb_w[k*NHEAD + 2];
            h3 += plk * pb_w[k*NHEAD + 3];
        }
        v = make_float4(h0, h1, h2, h3);
    }
    ((float4*)g_biasc)[slot] = v;
}

// ---------------- block-diagonal attention: 1 block/atom, 1 warp/head ----------------
__global__ void k_attn() {
    int i = blockIdx.x;
    int b = i / NATOM;
    int h = threadIdx.x >> 5, lane = threadIdx.x & 31;
    int s = g_gs[i], e = g_ge[i];
    const float* qrow = g_qkvg + (size_t)i * 512;
    float qd = qrow[h*DHEAD + lane];
    const float* biasrow = g_biasc + (size_t)i * MAXG * NHEAD + h;
    float m = -1e30f, l = 0.0f, acc = 0.0f;
    for (int j = s; j < e; j++) {
        const float* row = g_qkvg + (size_t)(b*NATOM + j) * 512;
        float sc = qd * row[DATOM + h*DHEAD + lane];
        #pragma unroll
        for (int o = 16; o; o >>= 1) sc += __shfl_xor_sync(0xffffffffu, sc, o);
        int slot = j - s;
        float bias = (slot < MAXG) ? biasrow[(size_t)slot * NHEAD] : 0.0f;
        sc = sc * 0.17677669529663687f + bias;
        float mn = fmaxf(m, sc);
        float corr = __expf(m - mn);
        float w = __expf(sc - mn);
        l = l * corr + w;
        acc = acc * corr + w * row[2*DATOM + h*DHEAD + lane];
        m = mn;
    }
    g_attout[(size_t)i * DATOM + h*DHEAD + lane] = acc / l;
}

// ---------------- segment mean ----------------
__global__ void k_segmean(const float* __restrict__ tok_b, float* __restrict__ out) {
    int seg = blockIdx.x;
    int b = seg / NTOK;
    int d = threadIdx.x;
    int s = g_ts[seg], c = g_tc[seg];
    float sum = 0.0f;
    for (int k = 0; k < c; k++)
        sum += g_feat[(size_t)(b*NATOM + s + k) * DMODEL + d];
    out[(size_t)seg * DMODEL + d] = c ? (sum / (float)c + tok_b[d]) : 0.0f;
}

// ---------------- launch ----------------
extern "C" void kernel_launch(void* const* d_in, const int* in_sizes, int n_in,
                              void* d_out, int out_size) {
    int shift = (in_sizes[4] == 1) ? 1 : 0;
    const float* c_atom    = (const float*)d_in[0];
    const float* p_lm      = (const float*)d_in[1];
    const int*   p_lm_idx  = (const int*)  d_in[2];
    const int*   token_idx = (const int*)  d_in[3];
    const float* ln_attn_g = (const float*)d_in[4+shift];
    const float* ln_attn_b = (const float*)d_in[5+shift];
    const float* w_q       = (const float*)d_in[6+shift];
    const float* w_k       = (const float*)d_in[7+shift];
    const float* w_v       = (const float*)d_in[8+shift];
    const float* w_g       = (const float*)d_in[9+shift];
    const float* w_o       = (const float*)d_in[10+shift];
    const float* pb_w      = (const float*)d_in[11+shift];
    const float* pb_b      = (const float*)d_in[12+shift];
    const float* ln_ff_g   = (const float*)d_in[13+shift];
    const float* ln_ff_b   = (const float*)d_in[14+shift];
    const float* sw_w1     = (const float*)d_in[15+shift];
    const float* sw_w2     = (const float*)d_in[16+shift];
    const float* sw_w3     = (const float*)d_in[17+shift];
    const float* tok_w     = (const float*)d_in[18+shift];
    const float* tok_b     = (const float*)d_in[19+shift];
    float* out = (float*)d_out;

    float *p_qn, *p_qkvg, *p_attout, *p_q1, *p_h, *p_u, *p_feat;
    cudaGetSymbolAddress((void**)&p_qn,     g_qn);
    cudaGetSymbolAddress((void**)&p_qkvg,   g_qkvg);
    cudaGetSymbolAddress((void**)&p_attout, g_attout);
    cudaGetSymbolAddress((void**)&p_q1,     g_q1);
    cudaGetSymbolAddress((void**)&p_h,      g_h);
    cudaGetSymbolAddress((void**)&p_u,      g_u);
    cudaGetSymbolAddress((void**)&p_feat,   g_feat);

    // dynamic smem opt-in (idempotent)
    const int SM128 = 2 * AST * (128 + 64) * 2;   // 104448 B
    const int SM64  = 2 * AST * ( 64 + 64) * 2;   //  69632 B
    const int SMFFN = 2 * AST * (128 + 128) * 2;  // 139264 B
    cudaFuncSetAttribute(k_mma<128,1,1>, cudaFuncAttributeMaxDynamicSharedMemorySize, SM128);
    cudaFuncSetAttribute(k_mma<128,1,0>, cudaFuncAttributeMaxDynamicSharedMemorySize, SM128);
    cudaFuncSetAttribute(k_mma<64,1,2>,  cudaFuncAttributeMaxDynamicSharedMemorySize, SM64);
    cudaFuncSetAttribute(k_mma<64,4,4>,  cudaFuncAttributeMaxDynamicSharedMemorySize, SM64);
    cudaFuncSetAttribute(k_mma_ffn,      cudaFuncAttributeMaxDynamicSharedMemorySize, SMFFN);

    // side stream for the bias chain (created once; same work every call)
    static cudaStream_t s_side = nullptr;
    static cudaEvent_t  e_fork = nullptr, e_join = nullptr;
    if (!s_side) {
        cudaStreamCreateWithFlags(&s_side, cudaStreamNonBlocking);
        cudaEventCreateWithFlags(&e_fork, cudaEventDisableTiming);
        cudaEventCreateWithFlags(&e_join, cudaEventDisableTiming);
    }

    // ---- fork: bias chain on side stream, overlapped with LN+QKVG ----
    cudaEventRecord(e_fork, 0);
    cudaStreamWaitEvent(s_side, e_fork, 0);
    k_prep    <<<ROWS*MAXG/4/256, 256, 0, s_side>>>(token_idx);
    k_scatmax <<<(BATCH*NPAIR)/256, 256, 0, s_side>>>(p_lm_idx, token_idx);
    k_biasfill<<<ROWS*MAXG/256, 256, 0, s_side>>>(p_lm, pb_w, pb_b);
    cudaEventRecord(e_join, s_side);

    // ---- main chain ----
    k_ln<<<ROWS/4, 128>>>(c_atom, ln_attn_g, ln_attn_b, p_qn);
    k_mma<128,1,1><<<dim3(8, ROWS/128), 256, SM128>>>(p_qn, 128, w_q, w_k, w_v, w_g, 128,
                                                      p_qkvg, 512, nullptr);

    cudaStreamWaitEvent(0, e_join, 0);
    k_attn<<<ROWS, 128>>>();

    k_mma<64,1,2><<<dim3(2, ROWS/64), 256, SM64>>>(p_attout, 128, w_o, w_o, w_o, w_o, 128,
                                                   nullptr, 0, c_atom);
    k_ln<<<ROWS/4, 128>>>(p_q1, ln_ff_g, ln_ff_b, p_h);
    k_mma_ffn<<<dim3(DFF/64, ROWS/128), 256, SMFFN>>>(p_h, sw_w1, sw_w2);
    k_mma<64,4,4><<<dim3(2, ROWS/64), 256, SM64>>>(p_u, 512, sw_w3, sw_w3, sw_w3, sw_w3, 128,
                                                   nullptr, 0, nullptr);
    k_mma<128,1,0><<<dim3(DMODEL/64, ROWS/128), 256, SM128>>>(p_q1, 128, tok_w, tok_w, tok_w, tok_w,
                                                              512, p_feat, 512, nullptr);
    k_segmean<<<BATCH*NTOK, DMODEL>>>(tok_b, out);
}

// round 13
// speedup vs baseline: 1.5537x; 1.0513x over previous
#include <cuda_runtime.h>
#include <cuda_bf16.h>
#include <math.h>
#include <stdint.h>

// ---------------- problem constants (fixed shapes) ----------------
#define BATCH   2
#define NATOM   2048
#define DATOM   128
#define NHEAD   4
#define DHEAD   32
#define DFF     512
#define DMODEL  512
#define NPAIR   16384
#define NTOK    512
#define ROWS    (BATCH*NATOM)      // 4096
#define NSEG    (BATCH*NTOK)       // 1024
#define MAXG    96                 // max atoms per token group (avg ~4; 96 astronomically safe)

// ---------------- static device scratch ----------------
__device__ float g_qkvg[ROWS*4*DATOM];        // [Q|K|V|G] fp32, stride 512 (attn needs fp32)
__device__ float g_q1  [ROWS*DATOM];          // fp32 residual stream
// split-bf16 operand buffers (hi, lo)
__device__ __align__(16) __nv_bfloat16 g_qn_h[ROWS*DATOM], g_qn_l[ROWS*DATOM];   // LN(c_atom)
__device__ __align__(16) __nv_bfloat16 g_ao_h[ROWS*DATOM], g_ao_l[ROWS*DATOM];   // attn out
__device__ __align__(16) __nv_bfloat16 g_hh [ROWS*DATOM], g_hl [ROWS*DATOM];     // LN_ff(q1)
__device__ __align__(16) __nv_bfloat16 g_uh [ROWS*DFF ],  g_ul [ROWS*DFF ];      // swiglu out
__device__ __align__(16) __nv_bfloat16 g_mqh[NSEG*DATOM], g_mql[NSEG*DATOM];     // segmean(q1)
// pre-split transposed weights ([n][k] layout)
__device__ __align__(16) __nv_bfloat16 g_wqkvg_h[4*128*128], g_wqkvg_l[4*128*128];
__device__ __align__(16) __nv_bfloat16 g_wo_h[128*128],  g_wo_l[128*128];
__device__ __align__(16) __nv_bfloat16 g_w1_h[512*128],  g_w1_l[512*128];
__device__ __align__(16) __nv_bfloat16 g_w2_h[512*128],  g_w2_l[512*128];
__device__ __align__(16) __nv_bfloat16 g_w3_h[128*512],  g_w3_l[128*512];
__device__ __align__(16) __nv_bfloat16 g_tw_h[512*128],  g_tw_l[512*128];
// bias scatter
__device__ __align__(16) float g_biasc[(size_t)ROWS*MAXG*NHEAD];
__device__ __align__(16) int   g_winc [(size_t)ROWS*MAXG];
__device__ int g_gs[ROWS], g_ge[ROWS];
__device__ int g_ts[NSEG], g_tc[NSEG];

// ---------------- helpers ----------------
__device__ __forceinline__ int d_lower_bound(const int* a, int n, int v) {
    int lo = 0, hi = n;
    while (lo < hi) { int m = (lo + hi) >> 1; if (a[m] < v) lo = m + 1; else hi = m; }
    return lo;
}
__device__ __forceinline__ int d_upper_bound(const int* a, int n, int v) {
    int lo = 0, hi = n;
    while (lo < hi) { int m = (lo + hi) >> 1; if (a[m] <= v) lo = m + 1; else hi = m; }
    return lo;
}
__device__ __forceinline__ float d_sigmoid(float x) { return 1.0f / (1.0f + __expf(-x)); }

__device__ __forceinline__ void mma_bf16(float d[4], const uint32_t a[4], const uint32_t b[2]) {
    asm volatile(
        "mma.sync.aligned.m16n8k16.row.col.f32.bf16.bf16.f32 "
        "{%0,%1,%2,%3}, {%4,%5,%6,%7}, {%8,%9}, {%0,%1,%2,%3};\n"
        : "+f"(d[0]), "+f"(d[1]), "+f"(d[2]), "+f"(d[3])
        : "r"(a[0]), "r"(a[1]), "r"(a[2]), "r"(a[3]), "r"(b[0]), "r"(b[1]));
}
__device__ __forceinline__ void ldsm_x4(uint32_t& d0, uint32_t& d1, uint32_t& d2, uint32_t& d3,
                                        uint32_t saddr) {
    asm volatile("ldmatrix.sync.aligned.m8n8.x4.shared.b16 {%0,%1,%2,%3}, [%4];"
                 : "=r"(d0), "=r"(d1), "=r"(d2), "=r"(d3) : "r"(saddr));
}
__device__ __forceinline__ void split2(float x, __nv_bfloat16& h, __nv_bfloat16& l) {
    h = __float2bfloat16(x);
    l = __float2bfloat16(x - __bfloat162float(h));
}

// ---------------- weight convert: src [K][N] fp32 -> dst [N][K] bf16 hi/lo ----------------
__global__ void k_wconv(const float* __restrict__ src, __nv_bfloat16* __restrict__ dh,
                        __nv_bfloat16* __restrict__ dl, int K, int N) {
    int gid = blockIdx.x * blockDim.x + threadIdx.x;
    if (gid >= K * N) return;
    int k = gid / N, n = gid % N;
    __nv_bfloat16 h, l;
    split2(src[gid], h, l);
    dh[n * K + k] = h;
    dl[n * K + k] = l;
}

// ---------------- LayerNorm: one warp per row of 128, writes bf16 hi/lo ----------------
__global__ void k_ln(const float* __restrict__ x, const float* __restrict__ g,
                     const float* __restrict__ b,
                     __nv_bfloat16* __restrict__ yh, __nv_bfloat16* __restrict__ yl) {
    int warp = (blockIdx.x * blockDim.x + threadIdx.x) >> 5;
    int lane = threadIdx.x & 31;
    if (warp >= ROWS) return;
    const float* xr = x + (size_t)warp * DATOM;
    float v0 = xr[lane], v1 = xr[lane+32], v2 = xr[lane+64], v3 = xr[lane+96];
    float s  = v0+v1+v2+v3;
    float sq = v0*v0+v1*v1+v2*v2+v3*v3;
    #pragma unroll
    for (int o = 16; o; o >>= 1) {
        s  += __shfl_xor_sync(0xffffffffu, s,  o);
        sq += __shfl_xor_sync(0xffffffffu, sq, o);
    }
    float mean = s * (1.0f/DATOM);
    float var  = sq * (1.0f/DATOM) - mean*mean;
    float inv  = rsqrtf(var + 1e-5f);
    size_t base = (size_t)warp * DATOM;
    #pragma unroll
    for (int q = 0; q < 4; q++) {
        int c = lane + q*32;
        float v = (q==0?v0:q==1?v1:q==2?v2:v3);
        float y = (v - mean)*inv*g[c] + b[c];
        __nv_bfloat16 h, l;
        split2(y, h, l);
        yh[base + c] = h;
        yl[base + c] = l;
    }
}

// ============================================================================
// Split-bf16 MMA GEMM. Operands are PRE-SPLIT bf16 (hi/lo). Load stage = pure
// uint4 copies (conflict-free). Full-K smem residency, ldmatrix fragments.
// B global layout is [n][k] (row stride ldbk = total K of that weight).
// EPI: 1 = qkvg weight-select, store fp32 C (ldc=512)
//      2 = wo gated-residual: g_q1 = aux + sigmoid(G)*acc
//      4 = w3 residual add:   g_q1 += acc
//      5 = tok: C = (g_tc[r]>0) ? acc + bias2[c] : 0
// ============================================================================
#define AST 136   // smem K-stride (bf16 elems); rows at 68-word stride -> LDSM conflict-free

template<int BM, int KTILES, int EPI>
__global__ __launch_bounds__(256) void k_mma(
    const __nv_bfloat16* __restrict__ Ahg, const __nv_bfloat16* __restrict__ Alg, int lda,
    const __nv_bfloat16* __restrict__ Bhg, const __nv_bfloat16* __restrict__ Blg, int ldbk,
    float* __restrict__ C, int ldc, const float* __restrict__ aux,
    const float* __restrict__ bias2) {
    constexpr int WR  = (BM == 128) ? 4 : 2;
    constexpr int WTM = BM / WR;            // 32
    constexpr int WTN = 64 / (8 / WR);      // 32 (BM=128) or 16 (BM=64)
    constexpr int MT  = WTM / 16;           // 2
    constexpr int NT  = WTN / 8;            // 4 or 2

    extern __shared__ __align__(16) char smraw[];
    __nv_bfloat16* Ah = (__nv_bfloat16*)smraw;
    __nv_bfloat16* Al = Ah + BM*AST;
    __nv_bfloat16* Bh = Al + BM*AST;
    __nv_bfloat16* Bl = Bh + 64*AST;

    int tid = threadIdx.x, warp = tid >> 5, lane = tid & 31;
    int wm = warp % WR, wn = warp / WR;
    int gq = lane >> 2, t4 = lane & 3;
    int bm = blockIdx.y * BM;
    int bx = blockIdx.x;

    size_t b_off;
    if (EPI == 1) b_off = (size_t)(bx >> 1) * 16384 + (size_t)(bx & 1) * 8192;
    else          b_off = (size_t)bx * 64 * ldbk;
    int cn = bx * 64;

    uint32_t aBaseH = (uint32_t)__cvta_generic_to_shared(Ah);
    uint32_t aBaseL = (uint32_t)__cvta_generic_to_shared(Al);
    uint32_t bBaseH = (uint32_t)__cvta_generic_to_shared(Bh);
    uint32_t bBaseL = (uint32_t)__cvta_generic_to_shared(Bl);
    int rA = wm*WTM + ((lane>>3)&1)*8 + (lane&7);
    int cA = (lane>>4)*8;
    int rB = wn*WTN + ((lane>>4)<<3) + (lane&7);
    int cB = ((lane>>3)&1)*8;

    float acc[MT][NT][4] = {};

    for (int kt = 0; kt < KTILES; kt++) {
        // ---- A tile: BM x 128 bf16 hi/lo, pure uint4 copies ----
        #pragma unroll
        for (int it = 0; it < BM/16; it++) {
            int idx = tid + it*256;
            int r = idx >> 4, c8 = (idx & 15) << 3;
            size_t go = (size_t)(bm + r) * lda + kt*128 + c8;
            *(uint4*)&Ah[r*AST + c8] = *(const uint4*)(Ahg + go);
            *(uint4*)&Al[r*AST + c8] = *(const uint4*)(Alg + go);
        }
        // ---- B tile: 64 x 128 bf16 hi/lo ----
        #pragma unroll
        for (int it = 0; it < 4; it++) {
            int idx = tid + it*256;
            int n = idx >> 4, c8 = (idx & 15) << 3;
            size_t go = b_off + (size_t)n * ldbk + kt*128 + c8;
            *(uint4*)&Bh[n*AST + c8] = *(const uint4*)(Bhg + go);
            *(uint4*)&Bl[n*AST + c8] = *(const uint4*)(Blg + go);
        }
        __syncthreads();

        #pragma unroll
        for (int kk = 0; kk < 8; kk++) {
            int kb = kk * 16;
            uint32_t afh[MT][4], afl[MT][4], bfh[NT][2], bfl[NT][2];
            #pragma unroll
            for (int mt = 0; mt < MT; mt++) {
                uint32_t off = (uint32_t)(((rA + mt*16)*AST + kb + cA) * 2);
                ldsm_x4(afh[mt][0], afh[mt][1], afh[mt][2], afh[mt][3], aBaseH + off);
                ldsm_x4(afl[mt][0], afl[mt][1], afl[mt][2], afl[mt][3], aBaseL + off);
            }
            #pragma unroll
            for (int ntp = 0; ntp < NT/2; ntp++) {
                uint32_t off = (uint32_t)(((rB + ntp*16)*AST + kb + cB) * 2);
                ldsm_x4(bfh[2*ntp][0], bfh[2*ntp][1], bfh[2*ntp+1][0], bfh[2*ntp+1][1], bBaseH + off);
                ldsm_x4(bfl[2*ntp][0], bfl[2*ntp][1], bfl[2*ntp+1][0], bfl[2*ntp+1][1], bBaseL + off);
            }
            #pragma unroll
            for (int mt = 0; mt < MT; mt++)
                #pragma unroll
                for (int nt = 0; nt < NT; nt++) {
                    mma_bf16(acc[mt][nt], afh[mt], bfh[nt]);
                    mma_bf16(acc[mt][nt], afh[mt], bfl[nt]);
                    mma_bf16(acc[mt][nt], afl[mt], bfh[nt]);
                }
        }
        if (KTILES > 1) __syncthreads();
    }

    // ---- epilogue ----
    #pragma unroll
    for (int mt = 0; mt < MT; mt++)
        #pragma unroll
        for (int nt = 0; nt < NT; nt++)
            #pragma unroll
            for (int ci = 0; ci < 4; ci++) {
                int r = bm + wm * WTM + mt * 16 + gq + ((ci >> 1) ? 8 : 0);
                int c = cn + wn * WTN + nt * 8 + 2 * t4 + (ci & 1);
                float v = acc[mt][nt][ci];
                if constexpr (EPI == 1) {
                    C[(size_t)r * ldc + c] = v;
                } else if constexpr (EPI == 2) {
                    float gt = g_qkvg[(size_t)r * 512 + 3*DATOM + c];
                    g_q1[(size_t)r * DATOM + c] =
                        aux[(size_t)r * DATOM + c] + d_sigmoid(gt) * v;
                } else if constexpr (EPI == 4) {
                    g_q1[(size_t)r * DATOM + c] += v;
                } else if constexpr (EPI == 5) {
                    C[(size_t)r * ldc + c] = (g_tc[r] > 0) ? v + bias2[c] : 0.0f;
                }
            }
}

// ---------- dual-B FFN MMA: g_u = silu(h@w1)*(h@w2); pre-split operands ----------
__global__ __launch_bounds__(256) void k_mma_ffn() {
    extern __shared__ __align__(16) char smraw[];
    __nv_bfloat16* Ah  = (__nv_bfloat16*)smraw;
    __nv_bfloat16* Al  = Ah  + 128*AST;
    __nv_bfloat16* B1h = Al  + 128*AST;
    __nv_bfloat16* B1l = B1h + 64*AST;
    __nv_bfloat16* B2h = B1l + 64*AST;
    __nv_bfloat16* B2l = B2h + 64*AST;

    int tid = threadIdx.x, warp = tid >> 5, lane = tid & 31;
    int wm = warp & 3, wn = warp >> 2;           // 4x2 warps, warptile 32x32
    int gq = lane >> 2, t4 = lane & 3;
    int bm = blockIdx.y * 128;
    int bn = blockIdx.x * 64;

    uint32_t aBaseH  = (uint32_t)__cvta_generic_to_shared(Ah);
    uint32_t aBaseL  = (uint32_t)__cvta_generic_to_shared(Al);
    uint32_t b1BaseH = (uint32_t)__cvta_generic_to_shared(B1h);
    uint32_t b1BaseL = (uint32_t)__cvta_generic_to_shared(B1l);
    uint32_t b2BaseH = (uint32_t)__cvta_generic_to_shared(B2h);
    uint32_t b2BaseL = (uint32_t)__cvta_generic_to_shared(B2l);
    int rA = wm*32 + ((lane>>3)&1)*8 + (lane&7);
    int cA = (lane>>4)*8;
    int rB = wn*32 + ((lane>>4)<<3) + (lane&7);
    int cB = ((lane>>3)&1)*8;

    float au[2][4][4] = {}, avv[2][4][4] = {};

    // ---- A tile (LN_ff output): 128 x 128 ----
    #pragma unroll
    for (int it = 0; it < 8; it++) {
        int idx = tid + it*256;
        int r = idx >> 4, c8 = (idx & 15) << 3;
        size_t go = (size_t)(bm + r) * 128 + c8;
        *(uint4*)&Ah[r*AST + c8] = *(const uint4*)(g_hh + go);
        *(uint4*)&Al[r*AST + c8] = *(const uint4*)(g_hl + go);
    }
    // ---- B1, B2 tiles: 64 x 128 each ----
    #pragma unroll
    for (int it = 0; it < 4; it++) {
        int idx = tid + it*256;
        int n = idx >> 4, c8 = (idx & 15) << 3;
        size_t go = (size_t)(bn + n) * 128 + c8;
        *(uint4*)&B1h[n*AST + c8] = *(const uint4*)(g_w1_h + go);
        *(uint4*)&B1l[n*AST + c8] = *(const uint4*)(g_w1_l + go);
        *(uint4*)&B2h[n*AST + c8] = *(const uint4*)(g_w2_h + go);
        *(uint4*)&B2l[n*AST + c8] = *(const uint4*)(g_w2_l + go);
    }
    __syncthreads();

    #pragma unroll
    for (int kk = 0; kk < 8; kk++) {
        int kb = kk * 16;
        uint32_t afh[2][4], afl[2][4];
        uint32_t b1f[4][2], b1g[4][2], b2f[4][2], b2g[4][2];
        #pragma unroll
        for (int mt = 0; mt < 2; mt++) {
            uint32_t off = (uint32_t)(((rA + mt*16)*AST + kb + cA) * 2);
            ldsm_x4(afh[mt][0], afh[mt][1], afh[mt][2], afh[mt][3], aBaseH + off);
            ldsm_x4(afl[mt][0], afl[mt][1], afl[mt][2], afl[mt][3], aBaseL + off);
        }
        #pragma unroll
        for (int ntp = 0; ntp < 2; ntp++) {
            uint32_t off = (uint32_t)(((rB + ntp*16)*AST + kb + cB) * 2);
            ldsm_x4(b1f[2*ntp][0], b1f[2*ntp][1], b1f[2*ntp+1][0], b1f[2*ntp+1][1], b1BaseH + off);
            ldsm_x4(b1g[2*ntp][0], b1g[2*ntp][1], b1g[2*ntp+1][0], b1g[2*ntp+1][1], b1BaseL + off);
            ldsm_x4(b2f[2*ntp][0], b2f[2*ntp][1], b2f[2*ntp+1][0], b2f[2*ntp+1][1], b2BaseH + off);
            ldsm_x4(b2g[2*ntp][0], b2g[2*ntp][1], b2g[2*ntp+1][0], b2g[2*ntp+1][1], b2BaseL + off);
        }
        #pragma unroll
        for (int nt = 0; nt < 4; nt++)
            #pragma unroll
            for (int mt = 0; mt < 2; mt++) {
                mma_bf16(au [mt][nt], afh[mt], b1f[nt]);
                mma_bf16(au [mt][nt], afh[mt], b1g[nt]);
                mma_bf16(au [mt][nt], afl[mt], b1f[nt]);
                mma_bf16(avv[mt][nt], afh[mt], b2f[nt]);
                mma_bf16(avv[mt][nt], afh[mt], b2g[nt]);
                mma_bf16(avv[mt][nt], afl[mt], b2f[nt]);
            }
    }
    #pragma unroll
    for (int mt = 0; mt < 2; mt++)
        #pragma unroll
        for (int nt = 0; nt < 4; nt++)
            #pragma unroll
            for (int ci = 0; ci < 4; ci++) {
                int r = bm + wm * 32 + mt * 16 + gq + ((ci >> 1) ? 8 : 0);
                int c = bn + wn * 32 + nt * 8 + 2 * t4 + (ci & 1);
                float uu = au[mt][nt][ci];
                float val = (uu * d_sigmoid(uu)) * avv[mt][nt][ci];
                __nv_bfloat16 h, l;
                split2(val, h, l);
                g_uh[(size_t)r * DFF + c] = h;
                g_ul[(size_t)r * DFF + c] = l;
            }
}

// ---------------- fused prep: group ranges + token ranges + winner zero ----------------
__global__ void k_prep(const int* __restrict__ tok) {
    int idx = blockIdx.x * blockDim.x + threadIdx.x;
    if (idx < ROWS*MAXG/4)
        ((int4*)g_winc)[idx] = make_int4(-1, -1, -1, -1);
    if (idx < ROWS) {
        int b = idx / NATOM, ii = idx % NATOM;
        const int* t = tok + b * NATOM;
        int v = t[ii];
        g_gs[idx] = d_lower_bound(t, NATOM, v);
        g_ge[idx] = d_upper_bound(t, NATOM, v);
    }
    if (idx < NSEG) {
        int b = idx / NTOK, tt = idx % NTOK;
        const int* ta = tok + b * NATOM;
        int lo = d_lower_bound(ta, NATOM, tt);
        int hi = d_upper_bound(ta, NATOM, tt);
        g_ts[idx] = lo; g_tc[idx] = hi - lo;
    }
}

// ---------------- pair scatter pass 1: last-write-wins winner ----------------
__global__ void k_scatmax(const int* __restrict__ plmidx, const int* __restrict__ tok) {
    int gid = blockIdx.x * blockDim.x + threadIdx.x;
    if (gid >= BATCH * NPAIR) return;
    int b = gid / NPAIR, p = gid % NPAIR;
    int src = plmidx[(size_t)gid*2], dst = plmidx[(size_t)gid*2 + 1];
    if (tok[b*NATOM + src] != tok[b*NATOM + dst]) return;
    int i = b*NATOM + src;
    int slot = dst - g_gs[i];
    if (slot >= 0 && slot < MAXG)
        atomicMax(&g_winc[(size_t)i * MAXG + slot], p);
}

// ---------------- pass 2: slot-ordered bias fill (coalesced; zeros losers) ----------------
__global__ void k_biasfill(const float* __restrict__ p_lm,
                           const float* __restrict__ pb_w, const float* __restrict__ pb_b) {
    int slot = blockIdx.x * blockDim.x + threadIdx.x;
    if (slot >= ROWS * MAXG) return;
    int w = g_winc[slot];
    float4 v = make_float4(0.f, 0.f, 0.f, 0.f);
    if (w >= 0) {
        int i = slot / MAXG;
        int b = i / NATOM;
        const float* pl = p_lm + ((size_t)b * NPAIR + w) * 16;
        float h0 = pb_b[0], h1 = pb_b[1], h2 = pb_b[2], h3 = pb_b[3];
        #pragma unroll
        for (int k = 0; k < 16; k++) {
            float plk = pl[k];
            h0 += plk * pb_w[k*NHEAD + 0];
            h1 += plk * pb_w[k*NHEAD + 1];
            h2 += plk * pb_w[k*NHEAD + 2];
            h3 += plk * pb_w[k*NHEAD + 3];
        }
        v = make_float4(h0, h1, h2, h3);
    }
    ((float4*)g_biasc)[slot] = v;
}

// ---------------- block-diagonal attention: 1 block/atom, 1 warp/head ----------------
__global__ void k_attn() {
    int i = blockIdx.x;
    int b = i / NATOM;
    int h = threadIdx.x >> 5, lane = threadIdx.x & 31;
    int s = g_gs[i], e = g_ge[i];
    const float* qrow = g_qkvg + (size_t)i * 512;
    float qd = qrow[h*DHEAD + lane];
    const float* biasrow = g_biasc + (size_t)i * MAXG * NHEAD + h;
    float m = -1e30f, l = 0.0f, acc = 0.0f;
    for (int j = s; j < e; j++) {
        const float* row = g_qkvg + (size_t)(b*NATOM + j) * 512;
        float sc = qd * row[DATOM + h*DHEAD + lane];
        #pragma unroll
        for (int o = 16; o; o >>= 1) sc += __shfl_xor_sync(0xffffffffu, sc, o);
        int slot = j - s;
        float bias = (slot < MAXG) ? biasrow[(size_t)slot * NHEAD] : 0.0f;
        sc = sc * 0.17677669529663687f + bias;
        float mn = fmaxf(m, sc);
        float corr = __expf(m - mn);
        float w = __expf(sc - mn);
        l = l * corr + w;
        acc = acc * corr + w * row[2*DATOM + h*DHEAD + lane];
        m = mn;
    }
    __nv_bfloat16 hh, ll;
    split2(acc / l, hh, ll);
    g_ao_h[(size_t)i * DATOM + h*DHEAD + lane] = hh;
    g_ao_l[(size_t)i * DATOM + h*DHEAD + lane] = ll;
}

// ---------------- segment mean of q1 (4096x128 -> 1024x128 bf16 hi/lo) ----------------
__global__ void k_segmeanq() {
    int seg = blockIdx.x;                 // 0..NSEG-1
    int b = seg / NTOK;
    int d = threadIdx.x;                  // 0..127
    int s = g_ts[seg], c = g_tc[seg];
    float sum = 0.0f;
    for (int k = 0; k < c; k++)
        sum += g_q1[(size_t)(b*NATOM + s + k) * DATOM + d];
    float m = c ? sum / (float)c : 0.0f;
    __nv_bfloat16 h, l;
    split2(m, h, l);
    g_mqh[(size_t)seg * DATOM + d] = h;
    g_mql[(size_t)seg * DATOM + d] = l;
}

// ---------------- launch ----------------
extern "C" void kernel_launch(void* const* d_in, const int* in_sizes, int n_in,
                              void* d_out, int out_size) {
    int shift = (in_sizes[4] == 1) ? 1 : 0;
    const float* c_atom    = (const float*)d_in[0];
    const float* p_lm      = (const float*)d_in[1];
    const int*   p_lm_idx  = (const int*)  d_in[2];
    const int*   token_idx = (const int*)  d_in[3];
    const float* ln_attn_g = (const float*)d_in[4+shift];
    const float* ln_attn_b = (const float*)d_in[5+shift];
    const float* w_q       = (const float*)d_in[6+shift];
    const float* w_k       = (const float*)d_in[7+shift];
    const float* w_v       = (const float*)d_in[8+shift];
    const float* w_g       = (const float*)d_in[9+shift];
    const float* w_o       = (const float*)d_in[10+shift];
    const float* pb_w      = (const float*)d_in[11+shift];
    const float* pb_b      = (const float*)d_in[12+shift];
    const float* ln_ff_g   = (const float*)d_in[13+shift];
    const float* ln_ff_b   = (const float*)d_in[14+shift];
    const float* sw_w1     = (const float*)d_in[15+shift];
    const float* sw_w2     = (const float*)d_in[16+shift];
    const float* sw_w3     = (const float*)d_in[17+shift];
    const float* tok_w     = (const float*)d_in[18+shift];
    const float* tok_b     = (const float*)d_in[19+shift];
    float* out = (float*)d_out;

    float *p_qkvg, *p_q1;
    cudaGetSymbolAddress((void**)&p_qkvg, g_qkvg);
    cudaGetSymbolAddress((void**)&p_q1,   g_q1);
    __nv_bfloat16 *p_qnh, *p_qnl, *p_aoh, *p_aol, *p_hh, *p_hl, *p_uh, *p_ul, *p_mqh, *p_mql;
    cudaGetSymbolAddress((void**)&p_qnh, g_qn_h);  cudaGetSymbolAddress((void**)&p_qnl, g_qn_l);
    cudaGetSymbolAddress((void**)&p_aoh, g_ao_h);  cudaGetSymbolAddress((void**)&p_aol, g_ao_l);
    cudaGetSymbolAddress((void**)&p_hh,  g_hh);    cudaGetSymbolAddress((void**)&p_hl,  g_hl);
    cudaGetSymbolAddress((void**)&p_uh,  g_uh);    cudaGetSymbolAddress((void**)&p_ul,  g_ul);
    cudaGetSymbolAddress((void**)&p_mqh, g_mqh);   cudaGetSymbolAddress((void**)&p_mql, g_mql);
    __nv_bfloat16 *p_wqh, *p_wql, *p_woh, *p_wol, *p_w1h, *p_w1l, *p_w2h, *p_w2l,
                  *p_w3h, *p_w3l, *p_twh, *p_twl;
    cudaGetSymbolAddress((void**)&p_wqh, g_wqkvg_h); cudaGetSymbolAddress((void**)&p_wql, g_wqkvg_l);
    cudaGetSymbolAddress((void**)&p_woh, g_wo_h);    cudaGetSymbolAddress((void**)&p_wol, g_wo_l);
    cudaGetSymbolAddress((void**)&p_w1h, g_w1_h);    cudaGetSymbolAddress((void**)&p_w1l, g_w1_l);
    cudaGetSymbolAddress((void**)&p_w2h, g_w2_h);    cudaGetSymbolAddress((void**)&p_w2l, g_w2_l);
    cudaGetSymbolAddress((void**)&p_w3h, g_w3_h);    cudaGetSymbolAddress((void**)&p_w3l, g_w3_l);
    cudaGetSymbolAddress((void**)&p_twh, g_tw_h);    cudaGetSymbolAddress((void**)&p_twl, g_tw_l);

    // dynamic smem opt-in (idempotent)
    const int SM128 = 2 * AST * (128 + 64) * 2;   // 104448 B
    const int SM64  = 2 * AST * ( 64 + 64) * 2;   //  69632 B
    const int SMFFN = 2 * AST * (128 + 128) * 2;  // 139264 B
    cudaFuncSetAttribute(k_mma<128,1,1>, cudaFuncAttributeMaxDynamicSharedMemorySize, SM128);
    cudaFuncSetAttribute(k_mma<64,1,2>,  cudaFuncAttributeMaxDynamicSharedMemorySize, SM64);
    cudaFuncSetAttribute(k_mma<64,4,4>,  cudaFuncAttributeMaxDynamicSharedMemorySize, SM64);
    cudaFuncSetAttribute(k_mma<128,1,5>, cudaFuncAttributeMaxDynamicSharedMemorySize, SM128);
    cudaFuncSetAttribute(k_mma_ffn,      cudaFuncAttributeMaxDynamicSharedMemorySize, SMFFN);

    // side stream (created once; identical work every call)
    static cudaStream_t s_side = nullptr;
    static cudaEvent_t  e_fork = nullptr, e_w1 = nullptr, e_join = nullptr;
    if (!s_side) {
        cudaStreamCreateWithFlags(&s_side, cudaStreamNonBlocking);
        cudaEventCreateWithFlags(&e_fork, cudaEventDisableTiming);
        cudaEventCreateWithFlags(&e_w1,   cudaEventDisableTiming);
        cudaEventCreateWithFlags(&e_join, cudaEventDisableTiming);
    }

    // ---- fork: weight conversion + bias chain on side stream ----
    cudaEventRecord(e_fork, 0);
    cudaStreamWaitEvent(s_side, e_fork, 0);
    // qkvg weights first (needed earliest)
    k_wconv<<<64, 256, 0, s_side>>>(w_q, p_wqh + 0*16384, p_wql + 0*16384, 128, 128);
    k_wconv<<<64, 256, 0, s_side>>>(w_k, p_wqh + 1*16384, p_wql + 1*16384, 128, 128);
    k_wconv<<<64, 256, 0, s_side>>>(w_v, p_wqh + 2*16384, p_wql + 2*16384, 128, 128);
    k_wconv<<<64, 256, 0, s_side>>>(w_g, p_wqh + 3*16384, p_wql + 3*16384, 128, 128);
    cudaEventRecord(e_w1, s_side);
    k_wconv<<<64,  256, 0, s_side>>>(w_o,   p_woh, p_wol, 128, 128);
    k_wconv<<<256, 256, 0, s_side>>>(sw_w1, p_w1h, p_w1l, 128, 512);
    k_wconv<<<256, 256, 0, s_side>>>(sw_w2, p_w2h, p_w2l, 128, 512);
    k_wconv<<<256, 256, 0, s_side>>>(sw_w3, p_w3h, p_w3l, 512, 128);
    k_wconv<<<256, 256, 0, s_side>>>(tok_w, p_twh, p_twl, 128, 512);
    k_prep    <<<ROWS*MAXG/4/256, 256, 0, s_side>>>(token_idx);
    k_scatmax <<<(BATCH*NPAIR)/256, 256, 0, s_side>>>(p_lm_idx, token_idx);
    k_biasfill<<<ROWS*MAXG/256, 256, 0, s_side>>>(p_lm, pb_w, pb_b);
    cudaEventRecord(e_join, s_side);

    // ---- main chain ----
    k_ln<<<ROWS/4, 128>>>(c_atom, ln_attn_g, ln_attn_b, p_qnh, p_qnl);
    cudaStreamWaitEvent(0, e_w1, 0);
    k_mma<128,1,1><<<dim3(8, ROWS/128), 256, SM128>>>(
        p_qnh, p_qnl, 128, p_wqh, p_wql, 128, p_qkvg, 512, nullptr, nullptr);

    cudaStreamWaitEvent(0, e_join, 0);   // bias + remaining weights ready
    k_attn<<<ROWS, 128>>>();

    k_mma<64,1,2><<<dim3(2, ROWS/64), 256, SM64>>>(
        p_aoh, p_aol, 128, p_woh, p_wol, 128, nullptr, 0, c_atom, nullptr);
    k_ln<<<ROWS/4, 128>>>(p_q1, ln_ff_g, ln_ff_b, p_hh, p_hl);
    k_mma_ffn<<<dim3(DFF/64, ROWS/128), 256, SMFFN>>>();
    k_mma<64,4,4><<<dim3(2, ROWS/64), 256, SM64>>>(
        p_uh, p_ul, 512, p_w3h, p_w3l, 512, nullptr, 0, nullptr, nullptr);

    // segment-mean BEFORE token projection (linearity), then small GEMM -> out
    k_segmeanq<<<NSEG, DATOM>>>();
    k_mma<128,1,5><<<dim3(DMODEL/64, NSEG/128), 256, SM128>>>(
        p_mqh, p_mql, 128, p_twh, p_twl, 128, out, DMODEL, nullptr, tok_b);
}

// round 15
// speedup vs baseline: 1.8611x; 1.1979x over previous
#include <cuda_runtime.h>
#include <cuda_bf16.h>
#include <math.h>
#include <stdint.h>

// ---------------- problem constants (fixed shapes) ----------------
#define BATCH   2
#define NATOM   2048
#define DATOM   128
#define NHEAD   4
#define DHEAD   32
#define DFF     512
#define DMODEL  512
#define NPAIR   16384
#define NTOK    512
#define ROWS    (BATCH*NATOM)      // 4096
#define NSEG    (BATCH*NTOK)       // 1024
#define MAXG    96                 // max atoms per token group (avg ~4; 96 astronomically safe)

// ---------------- static device scratch ----------------
__device__ float g_qkvg[ROWS*4*DATOM];        // [Q|K|V|G] fp32, stride 512 (attn needs fp32)
__device__ float g_q1  [ROWS*DATOM];          // fp32 residual stream
// split-bf16 operand buffers (hi, lo)
__device__ __align__(16) __nv_bfloat16 g_qn_h[ROWS*DATOM], g_qn_l[ROWS*DATOM];   // LN(c_atom)
__device__ __align__(16) __nv_bfloat16 g_ao_h[ROWS*DATOM], g_ao_l[ROWS*DATOM];   // attn out
__device__ __align__(16) __nv_bfloat16 g_hh [ROWS*DATOM], g_hl [ROWS*DATOM];     // LN_ff(q1)
__device__ __align__(16) __nv_bfloat16 g_uh [ROWS*DFF ],  g_ul [ROWS*DFF ];      // swiglu out
__device__ __align__(16) __nv_bfloat16 g_mqh[NSEG*DATOM], g_mql[NSEG*DATOM];     // segmean(q1)
// pre-split transposed weights ([n][k] layout)
__device__ __align__(16) __nv_bfloat16 g_wqkvg_h[4*128*128], g_wqkvg_l[4*128*128];
__device__ __align__(16) __nv_bfloat16 g_wo_h[128*128],  g_wo_l[128*128];
__device__ __align__(16) __nv_bfloat16 g_w1_h[512*128],  g_w1_l[512*128];
__device__ __align__(16) __nv_bfloat16 g_w2_h[512*128],  g_w2_l[512*128];
__device__ __align__(16) __nv_bfloat16 g_w3_h[128*512],  g_w3_l[128*512];
__device__ __align__(16) __nv_bfloat16 g_tw_h[512*128],  g_tw_l[512*128];
// bias scatter
__device__ __align__(16) float g_biasc[(size_t)ROWS*MAXG*NHEAD];
__device__ __align__(16) int   g_winc [(size_t)ROWS*MAXG];
__device__ int g_gs[ROWS], g_ge[ROWS];
__device__ int g_ts[NSEG], g_tc[NSEG];

// ---------------- helpers ----------------
__device__ __forceinline__ int d_lower_bound(const int* a, int n, int v) {
    int lo = 0, hi = n;
    while (lo < hi) { int m = (lo + hi) >> 1; if (a[m] < v) lo = m + 1; else hi = m; }
    return lo;
}
__device__ __forceinline__ int d_upper_bound(const int* a, int n, int v) {
    int lo = 0, hi = n;
    while (lo < hi) { int m = (lo + hi) >> 1; if (a[m] <= v) lo = m + 1; else hi = m; }
    return lo;
}
__device__ __forceinline__ float d_sigmoid(float x) { return 1.0f / (1.0f + __expf(-x)); }

__device__ __forceinline__ void mma_bf16(float d[4], const uint32_t a[4], const uint32_t b[2]) {
    asm volatile(
        "mma.sync.aligned.m16n8k16.row.col.f32.bf16.bf16.f32 "
        "{%0,%1,%2,%3}, {%4,%5,%6,%7}, {%8,%9}, {%0,%1,%2,%3};\n"
        : "+f"(d[0]), "+f"(d[1]), "+f"(d[2]), "+f"(d[3])
        : "r"(a[0]), "r"(a[1]), "r"(a[2]), "r"(a[3]), "r"(b[0]), "r"(b[1]));
}
__device__ __forceinline__ void ldsm_x4(uint32_t& d0, uint32_t& d1, uint32_t& d2, uint32_t& d3,
                                        uint32_t saddr) {
    asm volatile("ldmatrix.sync.aligned.m8n8.x4.shared.b16 {%0,%1,%2,%3}, [%4];"
                 : "=r"(d0), "=r"(d1), "=r"(d2), "=r"(d3) : "r"(saddr));
}
__device__ __forceinline__ void split2(float x, __nv_bfloat16& h, __nv_bfloat16& l) {
    h = __float2bfloat16(x);
    l = __float2bfloat16(x - __bfloat162float(h));
}

// ---------------- batched weight convert: all weights, ONE launch ----------------
// Each weight: src [K][N] fp32 -> dst [N][K] bf16 hi/lo. 32x32 smem-tiled transpose.
struct WDesc {
    const float* src;
    __nv_bfloat16* dh;
    __nv_bfloat16* dl;
    int K, N, t0;      // t0 = first tile index of this weight
};
struct WAll { WDesc w[9]; };
#define WC_TILES 336   // 5*16 (128x128) + 4*64 (128x512 or 512x128)

__global__ __launch_bounds__(256) void k_wconv_all(WAll wa) {
    __shared__ float sm[32][33];
    int bt = blockIdx.x;
    int wi = 8;
    #pragma unroll
    for (int i = 8; i >= 1; i--) if (bt < wa.w[i].t0) wi = i - 1;
    const WDesc& d = wa.w[wi];
    int t = bt - d.t0;
    int tiles_n = d.N >> 5;
    int tk = t / tiles_n, tn = t % tiles_n;
    int r = threadIdx.x >> 5, c = threadIdx.x & 31;
    #pragma unroll
    for (int i = 0; i < 4; i++) {
        int row = r + i*8;                         // k within tile
        sm[row][c] = d.src[(size_t)(tk*32 + row) * d.N + tn*32 + c];
    }
    __syncthreads();
    #pragma unroll
    for (int i = 0; i < 4; i++) {
        int row = r + i*8;                         // n within tile
        float v = sm[c][row];
        __nv_bfloat16 h, l;
        split2(v, h, l);
        size_t o = (size_t)(tn*32 + row) * d.K + tk*32 + c;
        d.dh[o] = h;
        d.dl[o] = l;
    }
}

// ---------------- LayerNorm: one warp per row of 128, writes bf16 hi/lo ----------------
__global__ void k_ln(const float* __restrict__ x, const float* __restrict__ g,
                     const float* __restrict__ b,
                     __nv_bfloat16* __restrict__ yh, __nv_bfloat16* __restrict__ yl) {
    int warp = (blockIdx.x * blockDim.x + threadIdx.x) >> 5;
    int lane = threadIdx.x & 31;
    if (warp >= ROWS) return;
    const float* xr = x + (size_t)warp * DATOM;
    float v0 = xr[lane], v1 = xr[lane+32], v2 = xr[lane+64], v3 = xr[lane+96];
    float s  = v0+v1+v2+v3;
    float sq = v0*v0+v1*v1+v2*v2+v3*v3;
    #pragma unroll
    for (int o = 16; o; o >>= 1) {
        s  += __shfl_xor_sync(0xffffffffu, s,  o);
        sq += __shfl_xor_sync(0xffffffffu, sq, o);
    }
    float mean = s * (1.0f/DATOM);
    float var  = sq * (1.0f/DATOM) - mean*mean;
    float inv  = rsqrtf(var + 1e-5f);
    size_t base = (size_t)warp * DATOM;
    #pragma unroll
    for (int q = 0; q < 4; q++) {
        int c = lane + q*32;
        float v = (q==0?v0:q==1?v1:q==2?v2:v3);
        float y = (v - mean)*inv*g[c] + b[c];
        __nv_bfloat16 h, l;
        split2(y, h, l);
        yh[base + c] = h;
        yl[base + c] = l;
    }
}

// ============================================================================
// Split-bf16 MMA GEMM. Pre-split bf16 operands, pure uint4 load stage,
// full-K smem residency, ldmatrix fragments.
// EPI: 1 = qkvg weight-select store; 2 = wo gated-residual; 4 = w3 res-add;
//      5 = tok: C = (g_tc[r]>0) ? acc + bias2[c] : 0
// ============================================================================
#define AST 136   // smem K-stride (bf16 elems); rows at 68-word stride -> LDSM conflict-free

template<int BM, int KTILES, int EPI>
__global__ __launch_bounds__(256) void k_mma(
    const __nv_bfloat16* __restrict__ Ahg, const __nv_bfloat16* __restrict__ Alg, int lda,
    const __nv_bfloat16* __restrict__ Bhg, const __nv_bfloat16* __restrict__ Blg, int ldbk,
    float* __restrict__ C, int ldc, const float* __restrict__ aux,
    const float* __restrict__ bias2) {
    constexpr int WR  = (BM == 128) ? 4 : 2;
    constexpr int WTM = BM / WR;            // 32
    constexpr int WTN = 64 / (8 / WR);      // 32 (BM=128) or 16 (BM=64)
    constexpr int MT  = WTM / 16;           // 2
    constexpr int NT  = WTN / 8;            // 4 or 2

    extern __shared__ __align__(16) char smraw[];
    __nv_bfloat16* Ah = (__nv_bfloat16*)smraw;
    __nv_bfloat16* Al = Ah + BM*AST;
    __nv_bfloat16* Bh = Al + BM*AST;
    __nv_bfloat16* Bl = Bh + 64*AST;

    int tid = threadIdx.x, warp = tid >> 5, lane = tid & 31;
    int wm = warp % WR, wn = warp / WR;
    int gq = lane >> 2, t4 = lane & 3;
    int bm = blockIdx.y * BM;
    int bx = blockIdx.x;

    size_t b_off;
    if (EPI == 1) b_off = (size_t)(bx >> 1) * 16384 + (size_t)(bx & 1) * 8192;
    else          b_off = (size_t)bx * 64 * ldbk;
    int cn = bx * 64;

    uint32_t aBaseH = (uint32_t)__cvta_generic_to_shared(Ah);
    uint32_t aBaseL = (uint32_t)__cvta_generic_to_shared(Al);
    uint32_t bBaseH = (uint32_t)__cvta_generic_to_shared(Bh);
    uint32_t bBaseL = (uint32_t)__cvta_generic_to_shared(Bl);
    int rA = wm*WTM + ((lane>>3)&1)*8 + (lane&7);
    int cA = (lane>>4)*8;
    int rB = wn*WTN + ((lane>>4)<<3) + (lane&7);
    int cB = ((lane>>3)&1)*8;

    float acc[MT][NT][4] = {};

    for (int kt = 0; kt < KTILES; kt++) {
        #pragma unroll
        for (int it = 0; it < BM/16; it++) {
            int idx = tid + it*256;
            int r = idx >> 4, c8 = (idx & 15) << 3;
            size_t go = (size_t)(bm + r) * lda + kt*128 + c8;
            *(uint4*)&Ah[r*AST + c8] = *(const uint4*)(Ahg + go);
            *(uint4*)&Al[r*AST + c8] = *(const uint4*)(Alg + go);
        }
        #pragma unroll
        for (int it = 0; it < 4; it++) {
            int idx = tid + it*256;
            int n = idx >> 4, c8 = (idx & 15) << 3;
            size_t go = b_off + (size_t)n * ldbk + kt*128 + c8;
            *(uint4*)&Bh[n*AST + c8] = *(const uint4*)(Bhg + go);
            *(uint4*)&Bl[n*AST + c8] = *(const uint4*)(Blg + go);
        }
        __syncthreads();

        #pragma unroll
        for (int kk = 0; kk < 8; kk++) {
            int kb = kk * 16;
            uint32_t afh[MT][4], afl[MT][4], bfh[NT][2], bfl[NT][2];
            #pragma unroll
            for (int mt = 0; mt < MT; mt++) {
                uint32_t off = (uint32_t)(((rA + mt*16)*AST + kb + cA) * 2);
                ldsm_x4(afh[mt][0], afh[mt][1], afh[mt][2], afh[mt][3], aBaseH + off);
                ldsm_x4(afl[mt][0], afl[mt][1], afl[mt][2], afl[mt][3], aBaseL + off);
            }
            #pragma unroll
            for (int ntp = 0; ntp < NT/2; ntp++) {
                uint32_t off = (uint32_t)(((rB + ntp*16)*AST + kb + cB) * 2);
                ldsm_x4(bfh[2*ntp][0], bfh[2*ntp][1], bfh[2*ntp+1][0], bfh[2*ntp+1][1], bBaseH + off);
                ldsm_x4(bfl[2*ntp][0], bfl[2*ntp][1], bfl[2*ntp+1][0], bfl[2*ntp+1][1], bBaseL + off);
            }
            #pragma unroll
            for (int mt = 0; mt < MT; mt++)
                #pragma unroll
                for (int nt = 0; nt < NT; nt++) {
                    mma_bf16(acc[mt][nt], afh[mt], bfh[nt]);
                    mma_bf16(acc[mt][nt], afh[mt], bfl[nt]);
                    mma_bf16(acc[mt][nt], afl[mt], bfh[nt]);
                }
        }
        if (KTILES > 1) __syncthreads();
    }

    #pragma unroll
    for (int mt = 0; mt < MT; mt++)
        #pragma unroll
        for (int nt = 0; nt < NT; nt++)
            #pragma unroll
            for (int ci = 0; ci < 4; ci++) {
                int r = bm + wm * WTM + mt * 16 + gq + ((ci >> 1) ? 8 : 0);
                int c = cn + wn * WTN + nt * 8 + 2 * t4 + (ci & 1);
                float v = acc[mt][nt][ci];
                if constexpr (EPI == 1) {
                    C[(size_t)r * ldc + c] = v;
                } else if constexpr (EPI == 2) {
                    float gt = g_qkvg[(size_t)r * 512 + 3*DATOM + c];
                    g_q1[(size_t)r * DATOM + c] =
                        aux[(size_t)r * DATOM + c] + d_sigmoid(gt) * v;
                } else if constexpr (EPI == 4) {
                    g_q1[(size_t)r * DATOM + c] += v;
                } else if constexpr (EPI == 5) {
                    C[(size_t)r * ldc + c] = (g_tc[r] > 0) ? v + bias2[c] : 0.0f;
                }
            }
}

// ---------- dual-B FFN MMA: g_u = silu(h@w1)*(h@w2); pre-split operands ----------
__global__ __launch_bounds__(256) void k_mma_ffn() {
    extern __shared__ __align__(16) char smraw[];
    __nv_bfloat16* Ah  = (__nv_bfloat16*)smraw;
    __nv_bfloat16* Al  = Ah  + 128*AST;
    __nv_bfloat16* B1h = Al  + 128*AST;
    __nv_bfloat16* B1l = B1h + 64*AST;
    __nv_bfloat16* B2h = B1l + 64*AST;
    __nv_bfloat16* B2l = B2h + 64*AST;

    int tid = threadIdx.x, warp = tid >> 5, lane = tid & 31;
    int wm = warp & 3, wn = warp >> 2;
    int gq = lane >> 2, t4 = lane & 3;
    int bm = blockIdx.y * 128;
    int bn = blockIdx.x * 64;

    uint32_t aBaseH  = (uint32_t)__cvta_generic_to_shared(Ah);
    uint32_t aBaseL  = (uint32_t)__cvta_generic_to_shared(Al);
    uint32_t b1BaseH = (uint32_t)__cvta_generic_to_shared(B1h);
    uint32_t b1BaseL = (uint32_t)__cvta_generic_to_shared(B1l);
    uint32_t b2BaseH = (uint32_t)__cvta_generic_to_shared(B2h);
    uint32_t b2BaseL = (uint32_t)__cvta_generic_to_shared(B2l);
    int rA = wm*32 + ((lane>>3)&1)*8 + (lane&7);
    int cA = (lane>>4)*8;
    int rB = wn*32 + ((lane>>4)<<3) + (lane&7);
    int cB = ((lane>>3)&1)*8;

    float au[2][4][4] = {}, avv[2][4][4] = {};

    #pragma unroll
    for (int it = 0; it < 8; it++) {
        int idx = tid + it*256;
        int r = idx >> 4, c8 = (idx & 15) << 3;
        size_t go = (size_t)(bm + r) * 128 + c8;
        *(uint4*)&Ah[r*AST + c8] = *(const uint4*)(g_hh + go);
        *(uint4*)&Al[r*AST + c8] = *(const uint4*)(g_hl + go);
    }
    #pragma unroll
    for (int it = 0; it < 4; it++) {
        int idx = tid + it*256;
        int n = idx >> 4, c8 = (idx & 15) << 3;
        size_t go = (size_t)(bn + n) * 128 + c8;
        *(uint4*)&B1h[n*AST + c8] = *(const uint4*)(g_w1_h + go);
        *(uint4*)&B1l[n*AST + c8] = *(const uint4*)(g_w1_l + go);
        *(uint4*)&B2h[n*AST + c8] = *(const uint4*)(g_w2_h + go);
        *(uint4*)&B2l[n*AST + c8] = *(const uint4*)(g_w2_l + go);
    }
    __syncthreads();

    #pragma unroll
    for (int kk = 0; kk < 8; kk++) {
        int kb = kk * 16;
        uint32_t afh[2][4], afl[2][4];
        uint32_t b1f[4][2], b1g[4][2], b2f[4][2], b2g[4][2];
        #pragma unroll
        for (int mt = 0; mt < 2; mt++) {
            uint32_t off = (uint32_t)(((rA + mt*16)*AST + kb + cA) * 2);
            ldsm_x4(afh[mt][0], afh[mt][1], afh[mt][2], afh[mt][3], aBaseH + off);
            ldsm_x4(afl[mt][0], afl[mt][1], afl[mt][2], afl[mt][3], aBaseL + off);
        }
        #pragma unroll
        for (int ntp = 0; ntp < 2; ntp++) {
            uint32_t off = (uint32_t)(((rB + ntp*16)*AST + kb + cB) * 2);
            ldsm_x4(b1f[2*ntp][0], b1f[2*ntp][1], b1f[2*ntp+1][0], b1f[2*ntp+1][1], b1BaseH + off);
            ldsm_x4(b1g[2*ntp][0], b1g[2*ntp][1], b1g[2*ntp+1][0], b1g[2*ntp+1][1], b1BaseL + off);
            ldsm_x4(b2f[2*ntp][0], b2f[2*ntp][1], b2f[2*ntp+1][0], b2f[2*ntp+1][1], b2BaseH + off);
            ldsm_x4(b2g[2*ntp][0], b2g[2*ntp][1], b2g[2*ntp+1][0], b2g[2*ntp+1][1], b2BaseL + off);
        }
        #pragma unroll
        for (int nt = 0; nt < 4; nt++)
            #pragma unroll
            for (int mt = 0; mt < 2; mt++) {
                mma_bf16(au [mt][nt], afh[mt], b1f[nt]);
                mma_bf16(au [mt][nt], afh[mt], b1g[nt]);
                mma_bf16(au [mt][nt], afl[mt], b1f[nt]);
                mma_bf16(avv[mt][nt], afh[mt], b2f[nt]);
                mma_bf16(avv[mt][nt], afh[mt], b2g[nt]);
                mma_bf16(avv[mt][nt], afl[mt], b2f[nt]);
            }
    }
    #pragma unroll
    for (int mt = 0; mt < 2; mt++)
        #pragma unroll
        for (int nt = 0; nt < 4; nt++)
            #pragma unroll
            for (int ci = 0; ci < 4; ci++) {
                int r = bm + wm * 32 + mt * 16 + gq + ((ci >> 1) ? 8 : 0);
                int c = bn + wn * 32 + nt * 8 + 2 * t4 + (ci & 1);
                float uu = au[mt][nt][ci];
                float val = (uu * d_sigmoid(uu)) * avv[mt][nt][ci];
                __nv_bfloat16 h, l;
                split2(val, h, l);
                g_uh[(size_t)r * DFF + c] = h;
                g_ul[(size_t)r * DFF + c] = l;
            }
}

// ---------------- fused prep: group ranges + token ranges + winner zero ----------------
__global__ void k_prep(const int* __restrict__ tok) {
    int idx = blockIdx.x * blockDim.x + threadIdx.x;
    if (idx < ROWS*MAXG/4)
        ((int4*)g_winc)[idx] = make_int4(-1, -1, -1, -1);
    if (idx < ROWS) {
        int b = idx / NATOM, ii = idx % NATOM;
        const int* t = tok + b * NATOM;
        int v = t[ii];
        g_gs[idx] = d_lower_bound(t, NATOM, v);
        g_ge[idx] = d_upper_bound(t, NATOM, v);
    }
    if (idx < NSEG) {
        int b = idx / NTOK, tt = idx % NTOK;
        const int* ta = tok + b * NATOM;
        int lo = d_lower_bound(ta, NATOM, tt);
        int hi = d_upper_bound(ta, NATOM, tt);
        g_ts[idx] = lo; g_tc[idx] = hi - lo;
    }
}

// ---------------- pair scatter pass 1: last-write-wins winner ----------------
__global__ void k_scatmax(const int* __restrict__ plmidx, const int* __restrict__ tok) {
    int gid = blockIdx.x * blockDim.x + threadIdx.x;
    if (gid >= BATCH * NPAIR) return;
    int b = gid / NPAIR, p = gid % NPAIR;
    int src = plmidx[(size_t)gid*2], dst = plmidx[(size_t)gid*2 + 1];
    if (tok[b*NATOM + src] != tok[b*NATOM + dst]) return;
    int i = b*NATOM + src;
    int slot = dst - g_gs[i];
    if (slot >= 0 && slot < MAXG)
        atomicMax(&g_winc[(size_t)i * MAXG + slot], p);
}

// ---------------- pass 2: slot-ordered bias fill (coalesced; zeros losers) ----------------
__global__ void k_biasfill(const float* __restrict__ p_lm,
                           const float* __restrict__ pb_w, const float* __restrict__ pb_b) {
    int slot = blockIdx.x * blockDim.x + threadIdx.x;
    if (slot >= ROWS * MAXG) return;
    int w = g_winc[slot];
    float4 v = make_float4(0.f, 0.f, 0.f, 0.f);
    if (w >= 0) {
        int i = slot / MAXG;
        int b = i / NATOM;
        const float* pl = p_lm + ((size_t)b * NPAIR + w) * 16;
        float h0 = pb_b[0], h1 = pb_b[1], h2 = pb_b[2], h3 = pb_b[3];
        #pragma unroll
        for (int k = 0; k < 16; k++) {
            float plk = pl[k];
            h0 += plk * pb_w[k*NHEAD + 0];
            h1 += plk * pb_w[k*NHEAD + 1];
            h2 += plk * pb_w[k*NHEAD + 2];
            h3 += plk * pb_w[k*NHEAD + 3];
        }
        v = make_float4(h0, h1, h2, h3);
    }
    ((float4*)g_biasc)[slot] = v;
}

// ---------------- block-diagonal attention: 1 block/atom, 1 warp/head ----------------
__global__ void k_attn() {
    int i = blockIdx.x;
    int b = i / NATOM;
    int h = threadIdx.x >> 5, lane = threadIdx.x & 31;
    int s = g_gs[i], e = g_ge[i];
    const float* qrow = g_qkvg + (size_t)i * 512;
    float qd = qrow[h*DHEAD + lane];
    const float* biasrow = g_biasc + (size_t)i * MAXG * NHEAD + h;
    float m = -1e30f, l = 0.0f, acc = 0.0f;
    for (int j = s; j < e; j++) {
        const float* row = g_qkvg + (size_t)(b*NATOM + j) * 512;
        float sc = qd * row[DATOM + h*DHEAD + lane];
        #pragma unroll
        for (int o = 16; o; o >>= 1) sc += __shfl_xor_sync(0xffffffffu, sc, o);
        int slot = j - s;
        float bias = (slot < MAXG) ? biasrow[(size_t)slot * NHEAD] : 0.0f;
        sc = sc * 0.17677669529663687f + bias;
        float mn = fmaxf(m, sc);
        float corr = __expf(m - mn);
        float w = __expf(sc - mn);
        l = l * corr + w;
        acc = acc * corr + w * row[2*DATOM + h*DHEAD + lane];
        m = mn;
    }
    __nv_bfloat16 hh, ll;
    split2(acc / l, hh, ll);
    g_ao_h[(size_t)i * DATOM + h*DHEAD + lane] = hh;
    g_ao_l[(size_t)i * DATOM + h*DHEAD + lane] = ll;
}

// ---------------- segment mean of q1 (4096x128 -> 1024x128 bf16 hi/lo) ----------------
__global__ void k_segmeanq() {
    int seg = blockIdx.x;
    int b = seg / NTOK;
    int d = threadIdx.x;
    int s = g_ts[seg], c = g_tc[seg];
    float sum = 0.0f;
    for (int k = 0; k < c; k++)
        sum += g_q1[(size_t)(b*NATOM + s + k) * DATOM + d];
    float m = c ? sum / (float)c : 0.0f;
    __nv_bfloat16 h, l;
    split2(m, h, l);
    g_mqh[(size_t)seg * DATOM + d] = h;
    g_mql[(size_t)seg * DATOM + d] = l;
}

// ---------------- launch ----------------
extern "C" void kernel_launch(void* const* d_in, const int* in_sizes, int n_in,
                              void* d_out, int out_size) {
    int shift = (in_sizes[4] == 1) ? 1 : 0;
    const float* c_atom    = (const float*)d_in[0];
    const float* p_lm      = (const float*)d_in[1];
    const int*   p_lm_idx  = (const int*)  d_in[2];
    const int*   token_idx = (const int*)  d_in[3];
    const float* ln_attn_g = (const float*)d_in[4+shift];
    const float* ln_attn_b = (const float*)d_in[5+shift];
    const float* w_q       = (const float*)d_in[6+shift];
    const float* w_k       = (const float*)d_in[7+shift];
    const float* w_v       = (const float*)d_in[8+shift];
    const float* w_g       = (const float*)d_in[9+shift];
    const float* w_o       = (const float*)d_in[10+shift];
    const float* pb_w      = (const float*)d_in[11+shift];
    const float* pb_b      = (const float*)d_in[12+shift];
    const float* ln_ff_g   = (const float*)d_in[13+shift];
    const float* ln_ff_b   = (const float*)d_in[14+shift];
    const float* sw_w1     = (const float*)d_in[15+shift];
    const float* sw_w2     = (const float*)d_in[16+shift];
    const float* sw_w3     = (const float*)d_in[17+shift];
    const float* tok_w     = (const float*)d_in[18+shift];
    const float* tok_b     = (const float*)d_in[19+shift];
    float* out = (float*)d_out;

    float *p_qkvg, *p_q1;
    cudaGetSymbolAddress((void**)&p_qkvg, g_qkvg);
    cudaGetSymbolAddress((void**)&p_q1,   g_q1);
    __nv_bfloat16 *p_qnh, *p_qnl, *p_aoh, *p_aol, *p_hh, *p_hl, *p_uh, *p_ul, *p_mqh, *p_mql;
    cudaGetSymbolAddress((void**)&p_qnh, g_qn_h);  cudaGetSymbolAddress((void**)&p_qnl, g_qn_l);
    cudaGetSymbolAddress((void**)&p_aoh, g_ao_h);  cudaGetSymbolAddress((void**)&p_aol, g_ao_l);
    cudaGetSymbolAddress((void**)&p_hh,  g_hh);    cudaGetSymbolAddress((void**)&p_hl,  g_hl);
    cudaGetSymbolAddress((void**)&p_uh,  g_uh);    cudaGetSymbolAddress((void**)&p_ul,  g_ul);
    cudaGetSymbolAddress((void**)&p_mqh, g_mqh);   cudaGetSymbolAddress((void**)&p_mql, g_mql);
    __nv_bfloat16 *p_wqh, *p_wql, *p_woh, *p_wol, *p_w1h, *p_w1l, *p_w2h, *p_w2l,
                  *p_w3h, *p_w3l, *p_twh, *p_twl;
    cudaGetSymbolAddress((void**)&p_wqh, g_wqkvg_h); cudaGetSymbolAddress((void**)&p_wql, g_wqkvg_l);
    cudaGetSymbolAddress((void**)&p_woh, g_wo_h);    cudaGetSymbolAddress((void**)&p_wol, g_wo_l);
    cudaGetSymbolAddress((void**)&p_w1h, g_w1_h);    cudaGetSymbolAddress((void**)&p_w1l, g_w1_l);
    cudaGetSymbolAddress((void**)&p_w2h, g_w2_h);    cudaGetSymbolAddress((void**)&p_w2l, g_w2_l);
    cudaGetSymbolAddress((void**)&p_w3h, g_w3_h);    cudaGetSymbolAddress((void**)&p_w3l, g_w3_l);
    cudaGetSymbolAddress((void**)&p_twh, g_tw_h);    cudaGetSymbolAddress((void**)&p_twl, g_tw_l);

    // dynamic smem opt-in (idempotent)
    const int SM128 = 2 * AST * (128 + 64) * 2;   // 104448 B
    const int SM64  = 2 * AST * ( 64 + 64) * 2;   //  69632 B
    const int SMFFN = 2 * AST * (128 + 128) * 2;  // 139264 B
    cudaFuncSetAttribute(k_mma<128,1,1>, cudaFuncAttributeMaxDynamicSharedMemorySize, SM128);
    cudaFuncSetAttribute(k_mma<64,1,2>,  cudaFuncAttributeMaxDynamicSharedMemorySize, SM64);
    cudaFuncSetAttribute(k_mma<64,4,4>,  cudaFuncAttributeMaxDynamicSharedMemorySize, SM64);
    cudaFuncSetAttribute(k_mma<128,1,5>, cudaFuncAttributeMaxDynamicSharedMemorySize, SM128);
    cudaFuncSetAttribute(k_mma_ffn,      cudaFuncAttributeMaxDynamicSharedMemorySize, SMFFN);

    // side stream (created once; identical work every call)
    static cudaStream_t s_side = nullptr;
    static cudaEvent_t  e_fork = nullptr, e_wc = nullptr, e_join = nullptr;
    if (!s_side) {
        cudaStreamCreateWithFlags(&s_side, cudaStreamNonBlocking);
        cudaEventCreateWithFlags(&e_fork, cudaEventDisableTiming);
        cudaEventCreateWithFlags(&e_wc,   cudaEventDisableTiming);
        cudaEventCreateWithFlags(&e_join, cudaEventDisableTiming);
    }

    // ---- descriptor table: tiles t0 cumulative (16 per 128x128, 64 per 128x512) ----
    WAll wa;
    wa.w[0] = { w_q,   p_wqh + 0*16384, p_wql + 0*16384, 128, 128,   0 };
    wa.w[1] = { w_k,   p_wqh + 1*16384, p_wql + 1*16384, 128, 128,  16 };
    wa.w[2] = { w_v,   p_wqh + 2*16384, p_wql + 2*16384, 128, 128,  32 };
    wa.w[3] = { w_g,   p_wqh + 3*16384, p_wql + 3*16384, 128, 128,  48 };
    wa.w[4] = { w_o,   p_woh,           p_wol,           128, 128,  64 };
    wa.w[5] = { sw_w1, p_w1h,           p_w1l,           128, 512,  80 };
    wa.w[6] = { sw_w2, p_w2h,           p_w2l,           128, 512, 144 };
    wa.w[7] = { sw_w3, p_w3h,           p_w3l,           512, 128, 208 };
    wa.w[8] = { tok_w, p_twh,           p_twl,           128, 512, 272 };

    // ---- fork: ONE weight-convert launch + bias chain on side stream ----
    cudaEventRecord(e_fork, 0);
    cudaStreamWaitEvent(s_side, e_fork, 0);
    k_wconv_all<<<WC_TILES, 256, 0, s_side>>>(wa);
    cudaEventRecord(e_wc, s_side);
    k_prep    <<<ROWS*MAXG/4/256, 256, 0, s_side>>>(token_idx);
    k_scatmax <<<(BATCH*NPAIR)/256, 256, 0, s_side>>>(p_lm_idx, token_idx);
    k_biasfill<<<ROWS*MAXG/256, 256, 0, s_side>>>(p_lm, pb_w, pb_b);
    cudaEventRecord(e_join, s_side);

    // ---- main chain ----
    k_ln<<<ROWS/4, 128>>>(c_atom, ln_attn_g, ln_attn_b, p_qnh, p_qnl);
    cudaStreamWaitEvent(0, e_wc, 0);
    k_mma<128,1,1><<<dim3(8, ROWS/128), 256, SM128>>>(
        p_qnh, p_qnl, 128, p_wqh, p_wql, 128, p_qkvg, 512, nullptr, nullptr);

    cudaStreamWaitEvent(0, e_join, 0);   // bias ready
    k_attn<<<ROWS, 128>>>();

    k_mma<64,1,2><<<dim3(2, ROWS/64), 256, SM64>>>(
        p_aoh, p_aol, 128, p_woh, p_wol, 128, nullptr, 0, c_atom, nullptr);
    k_ln<<<ROWS/4, 128>>>(p_q1, ln_ff_g, ln_ff_b, p_hh, p_hl);
    k_mma_ffn<<<dim3(DFF/64, ROWS/128), 256, SMFFN>>>();
    k_mma<64,4,4><<<dim3(2, ROWS/64), 256, SM64>>>(
        p_uh, p_ul, 512, p_w3h, p_w3l, 512, nullptr, 0, nullptr, nullptr);

    // segment-mean BEFORE token projection (linearity), then small GEMM -> out
    k_segmeanq<<<NSEG, DATOM>>>();
    k_mma<128,1,5><<<dim3(DMODEL/64, NSEG/128), 256, SM128>>>(
        p_mqh, p_mql, 128, p_twh, p_twl, 128, out, DMODEL, nullptr, tok_b);
}

// round 16
// speedup vs baseline: 1.9092x; 1.0258x over previous
#include <cuda_runtime.h>
#include <cuda_bf16.h>
#include <math.h>
#include <stdint.h>

// ---------------- problem constants (fixed shapes) ----------------
#define BATCH   2
#define NATOM   2048
#define DATOM   128
#define NHEAD   4
#define DHEAD   32
#define DFF     512
#define DMODEL  512
#define NPAIR   16384
#define NTOK    512
#define ROWS    (BATCH*NATOM)      // 4096
#define NSEG    (BATCH*NTOK)       // 1024
#define MAXG    32                 // max atoms per token group (Poisson(4); P(>32) ~ 1e-17)

// ---------------- static device scratch ----------------
__device__ float g_qkvg[ROWS*4*DATOM];        // [Q|K|V|G] fp32, stride 512 (attn needs fp32)
__device__ float g_q1  [ROWS*DATOM];          // fp32 residual stream
// split-bf16 operand buffers (hi, lo)
__device__ __align__(16) __nv_bfloat16 g_qn_h[ROWS*DATOM], g_qn_l[ROWS*DATOM];   // LN(c_atom)
__device__ __align__(16) __nv_bfloat16 g_ao_h[ROWS*DATOM], g_ao_l[ROWS*DATOM];   // attn out
__device__ __align__(16) __nv_bfloat16 g_hh [ROWS*DATOM], g_hl [ROWS*DATOM];     // LN_ff(q1)
__device__ __align__(16) __nv_bfloat16 g_uh [ROWS*DFF ],  g_ul [ROWS*DFF ];      // swiglu out
__device__ __align__(16) __nv_bfloat16 g_mqh[NSEG*DATOM], g_mql[NSEG*DATOM];     // segmean(q1)
// pre-split transposed weights ([n][k] layout)
__device__ __align__(16) __nv_bfloat16 g_wqkvg_h[4*128*128], g_wqkvg_l[4*128*128];
__device__ __align__(16) __nv_bfloat16 g_wo_h[128*128],  g_wo_l[128*128];
__device__ __align__(16) __nv_bfloat16 g_w1_h[512*128],  g_w1_l[512*128];
__device__ __align__(16) __nv_bfloat16 g_w2_h[512*128],  g_w2_l[512*128];
__device__ __align__(16) __nv_bfloat16 g_w3_h[128*512],  g_w3_l[128*512];
__device__ __align__(16) __nv_bfloat16 g_tw_h[512*128],  g_tw_l[512*128];
// bias scatter
__device__ __align__(16) float g_biasc[(size_t)ROWS*MAXG*NHEAD];
__device__ __align__(16) int   g_winc [(size_t)ROWS*MAXG];
__device__ int g_gs[ROWS], g_ge[ROWS];
__device__ int g_ts[NSEG], g_tc[NSEG];

// ---------------- helpers ----------------
__device__ __forceinline__ int d_lower_bound(const int* a, int n, int v) {
    int lo = 0, hi = n;
    while (lo < hi) { int m = (lo + hi) >> 1; if (a[m] < v) lo = m + 1; else hi = m; }
    return lo;
}
__device__ __forceinline__ int d_upper_bound(const int* a, int n, int v) {
    int lo = 0, hi = n;
    while (lo < hi) { int m = (lo + hi) >> 1; if (a[m] <= v) lo = m + 1; else hi = m; }
    return lo;
}
__device__ __forceinline__ float d_sigmoid(float x) { return 1.0f / (1.0f + __expf(-x)); }

__device__ __forceinline__ void mma_bf16(float d[4], const uint32_t a[4], const uint32_t b[2]) {
    asm volatile(
        "mma.sync.aligned.m16n8k16.row.col.f32.bf16.bf16.f32 "
        "{%0,%1,%2,%3}, {%4,%5,%6,%7}, {%8,%9}, {%0,%1,%2,%3};\n"
        : "+f"(d[0]), "+f"(d[1]), "+f"(d[2]), "+f"(d[3])
        : "r"(a[0]), "r"(a[1]), "r"(a[2]), "r"(a[3]), "r"(b[0]), "r"(b[1]));
}
__device__ __forceinline__ void ldsm_x4(uint32_t& d0, uint32_t& d1, uint32_t& d2, uint32_t& d3,
                                        uint32_t saddr) {
    asm volatile("ldmatrix.sync.aligned.m8n8.x4.shared.b16 {%0,%1,%2,%3}, [%4];"
                 : "=r"(d0), "=r"(d1), "=r"(d2), "=r"(d3) : "r"(saddr));
}
__device__ __forceinline__ void split2(float x, __nv_bfloat16& h, __nv_bfloat16& l) {
    h = __float2bfloat16(x);
    l = __float2bfloat16(x - __bfloat162float(h));
}

// ---------------- batched weight convert: all weights, ONE launch ----------------
struct WDesc {
    const float* src;
    __nv_bfloat16* dh;
    __nv_bfloat16* dl;
    int K, N, t0;
};
struct WAll { WDesc w[9]; };
#define WC_TILES 336

__global__ __launch_bounds__(256) void k_wconv_all(WAll wa) {
    __shared__ float sm[32][33];
    int bt = blockIdx.x;
    int wi = 8;
    #pragma unroll
    for (int i = 8; i >= 1; i--) if (bt < wa.w[i].t0) wi = i - 1;
    const WDesc& d = wa.w[wi];
    int t = bt - d.t0;
    int tiles_n = d.N >> 5;
    int tk = t / tiles_n, tn = t % tiles_n;
    int r = threadIdx.x >> 5, c = threadIdx.x & 31;
    #pragma unroll
    for (int i = 0; i < 4; i++) {
        int row = r + i*8;
        sm[row][c] = d.src[(size_t)(tk*32 + row) * d.N + tn*32 + c];
    }
    __syncthreads();
    #pragma unroll
    for (int i = 0; i < 4; i++) {
        int row = r + i*8;
        float v = sm[c][row];
        __nv_bfloat16 h, l;
        split2(v, h, l);
        size_t o = (size_t)(tn*32 + row) * d.K + tk*32 + c;
        d.dh[o] = h;
        d.dl[o] = l;
    }
}

// ---------------- LayerNorm: one warp per row of 128, writes bf16 hi/lo ----------------
__global__ void k_ln(const float* __restrict__ x, const float* __restrict__ g,
                     const float* __restrict__ b,
                     __nv_bfloat16* __restrict__ yh, __nv_bfloat16* __restrict__ yl) {
    int warp = (blockIdx.x * blockDim.x + threadIdx.x) >> 5;
    int lane = threadIdx.x & 31;
    if (warp >= ROWS) return;
    const float* xr = x + (size_t)warp * DATOM;
    float v0 = xr[lane], v1 = xr[lane+32], v2 = xr[lane+64], v3 = xr[lane+96];
    float s  = v0+v1+v2+v3;
    float sq = v0*v0+v1*v1+v2*v2+v3*v3;
    #pragma unroll
    for (int o = 16; o; o >>= 1) {
        s  += __shfl_xor_sync(0xffffffffu, s,  o);
        sq += __shfl_xor_sync(0xffffffffu, sq, o);
    }
    float mean = s * (1.0f/DATOM);
    float var  = sq * (1.0f/DATOM) - mean*mean;
    float inv  = rsqrtf(var + 1e-5f);
    size_t base = (size_t)warp * DATOM;
    #pragma unroll
    for (int q = 0; q < 4; q++) {
        int c = lane + q*32;
        float v = (q==0?v0:q==1?v1:q==2?v2:v3);
        float y = (v - mean)*inv*g[c] + b[c];
        __nv_bfloat16 h, l;
        split2(y, h, l);
        yh[base + c] = h;
        yl[base + c] = l;
    }
}

// ============================================================================
// Split-bf16 MMA GEMM. Pre-split bf16 operands, pure uint4 load stage,
// K chunked by 64 (single buffer) -> small smem -> 3-6 CTAs/SM for CTA-level
// load/compute overlap. ldmatrix fragments.
// EPI: 1 = qkvg weight-select store; 2 = wo gated-residual; 4 = w3 res-add;
//      5 = tok: C = (g_tc[r]>0) ? acc + bias2[c] : 0
// NK64 = K / 64 chunks.
// ============================================================================
#define AST 72   // smem K-stride (bf16); 36 words = 4 mod 32 -> LDSM conflict-free

template<int BM, int NK64, int EPI>
__global__ __launch_bounds__(256) void k_mma(
    const __nv_bfloat16* __restrict__ Ahg, const __nv_bfloat16* __restrict__ Alg, int lda,
    const __nv_bfloat16* __restrict__ Bhg, const __nv_bfloat16* __restrict__ Blg, int ldbk,
    float* __restrict__ C, int ldc, const float* __restrict__ aux,
    const float* __restrict__ bias2) {
    constexpr int WR  = (BM == 128) ? 4 : 2;
    constexpr int WTM = BM / WR;            // 32
    constexpr int WTN = 64 / (8 / WR);      // 32 (BM=128) or 16 (BM=64)
    constexpr int MT  = WTM / 16;           // 2
    constexpr int NT  = WTN / 8;            // 4 or 2

    extern __shared__ __align__(16) char smraw[];
    __nv_bfloat16* Ah = (__nv_bfloat16*)smraw;
    __nv_bfloat16* Al = Ah + BM*AST;
    __nv_bfloat16* Bh = Al + BM*AST;
    __nv_bfloat16* Bl = Bh + 64*AST;

    int tid = threadIdx.x, warp = tid >> 5, lane = tid & 31;
    int wm = warp % WR, wn = warp / WR;
    int gq = lane >> 2, t4 = lane & 3;
    int bm = blockIdx.y * BM;
    int bx = blockIdx.x;

    size_t b_off;
    if (EPI == 1) b_off = (size_t)(bx >> 1) * 16384 + (size_t)(bx & 1) * 8192;
    else          b_off = (size_t)bx * 64 * ldbk;
    int cn = bx * 64;

    uint32_t aBaseH = (uint32_t)__cvta_generic_to_shared(Ah);
    uint32_t aBaseL = (uint32_t)__cvta_generic_to_shared(Al);
    uint32_t bBaseH = (uint32_t)__cvta_generic_to_shared(Bh);
    uint32_t bBaseL = (uint32_t)__cvta_generic_to_shared(Bl);
    int rA = wm*WTM + ((lane>>3)&1)*8 + (lane&7);
    int cA = (lane>>4)*8;
    int rB = wn*WTN + ((lane>>4)<<3) + (lane&7);
    int cB = ((lane>>3)&1)*8;

    float acc[MT][NT][4] = {};

    for (int nk = 0; nk < NK64; nk++) {
        int kc0 = nk * 64;
        // ---- A chunk: BM x 64 bf16 hi/lo ----
        #pragma unroll
        for (int it = 0; it < BM/32; it++) {
            int idx = tid + it*256;
            int r = idx >> 3, c8 = (idx & 7) << 3;
            size_t go = (size_t)(bm + r) * lda + kc0 + c8;
            *(uint4*)&Ah[r*AST + c8] = *(const uint4*)(Ahg + go);
            *(uint4*)&Al[r*AST + c8] = *(const uint4*)(Alg + go);
        }
        // ---- B chunk: 64 x 64 bf16 hi/lo ----
        #pragma unroll
        for (int it = 0; it < 2; it++) {
            int idx = tid + it*256;
            int n = idx >> 3, c8 = (idx & 7) << 3;
            size_t go = b_off + (size_t)n * ldbk + kc0 + c8;
            *(uint4*)&Bh[n*AST + c8] = *(const uint4*)(Bhg + go);
            *(uint4*)&Bl[n*AST + c8] = *(const uint4*)(Blg + go);
        }
        __syncthreads();

        #pragma unroll
        for (int kk = 0; kk < 4; kk++) {
            int kb = kk * 16;
            uint32_t afh[MT][4], afl[MT][4], bfh[NT][2], bfl[NT][2];
            #pragma unroll
            for (int mt = 0; mt < MT; mt++) {
                uint32_t off = (uint32_t)(((rA + mt*16)*AST + kb + cA) * 2);
                ldsm_x4(afh[mt][0], afh[mt][1], afh[mt][2], afh[mt][3], aBaseH + off);
                ldsm_x4(afl[mt][0], afl[mt][1], afl[mt][2], afl[mt][3], aBaseL + off);
            }
            #pragma unroll
            for (int ntp = 0; ntp < NT/2; ntp++) {
                uint32_t off = (uint32_t)(((rB + ntp*16)*AST + kb + cB) * 2);
                ldsm_x4(bfh[2*ntp][0], bfh[2*ntp][1], bfh[2*ntp+1][0], bfh[2*ntp+1][1], bBaseH + off);
                ldsm_x4(bfl[2*ntp][0], bfl[2*ntp][1], bfl[2*ntp+1][0], bfl[2*ntp+1][1], bBaseL + off);
            }
            #pragma unroll
            for (int mt = 0; mt < MT; mt++)
                #pragma unroll
                for (int nt = 0; nt < NT; nt++) {
                    mma_bf16(acc[mt][nt], afh[mt], bfh[nt]);
                    mma_bf16(acc[mt][nt], afh[mt], bfl[nt]);
                    mma_bf16(acc[mt][nt], afl[mt], bfh[nt]);
                }
        }
        if (nk + 1 < NK64) __syncthreads();
    }

    #pragma unroll
    for (int mt = 0; mt < MT; mt++)
        #pragma unroll
        for (int nt = 0; nt < NT; nt++)
            #pragma unroll
            for (int ci = 0; ci < 4; ci++) {
                int r = bm + wm * WTM + mt * 16 + gq + ((ci >> 1) ? 8 : 0);
                int c = cn + wn * WTN + nt * 8 + 2 * t4 + (ci & 1);
                float v = acc[mt][nt][ci];
                if constexpr (EPI == 1) {
                    C[(size_t)r * ldc + c] = v;
                } else if constexpr (EPI == 2) {
                    float gt = g_qkvg[(size_t)r * 512 + 3*DATOM + c];
                    g_q1[(size_t)r * DATOM + c] =
                        aux[(size_t)r * DATOM + c] + d_sigmoid(gt) * v;
                } else if constexpr (EPI == 4) {
                    g_q1[(size_t)r * DATOM + c] += v;
                } else if constexpr (EPI == 5) {
                    C[(size_t)r * ldc + c] = (g_tc[r] > 0) ? v + bias2[c] : 0.0f;
                }
            }
}

// ---------- dual-B FFN MMA: g_u = silu(h@w1)*(h@w2); K chunked by 64 ----------
__global__ __launch_bounds__(256) void k_mma_ffn() {
    extern __shared__ __align__(16) char smraw[];
    __nv_bfloat16* Ah  = (__nv_bfloat16*)smraw;
    __nv_bfloat16* Al  = Ah  + 128*AST;
    __nv_bfloat16* B1h = Al  + 128*AST;
    __nv_bfloat16* B1l = B1h + 64*AST;
    __nv_bfloat16* B2h = B1l + 64*AST;
    __nv_bfloat16* B2l = B2h + 64*AST;

    int tid = threadIdx.x, warp = tid >> 5, lane = tid & 31;
    int wm = warp & 3, wn = warp >> 2;
    int gq = lane >> 2, t4 = lane & 3;
    int bm = blockIdx.y * 128;
    int bn = blockIdx.x * 64;

    uint32_t aBaseH  = (uint32_t)__cvta_generic_to_shared(Ah);
    uint32_t aBaseL  = (uint32_t)__cvta_generic_to_shared(Al);
    uint32_t b1BaseH = (uint32_t)__cvta_generic_to_shared(B1h);
    uint32_t b1BaseL = (uint32_t)__cvta_generic_to_shared(B1l);
    uint32_t b2BaseH = (uint32_t)__cvta_generic_to_shared(B2h);
    uint32_t b2BaseL = (uint32_t)__cvta_generic_to_shared(B2l);
    int rA = wm*32 + ((lane>>3)&1)*8 + (lane&7);
    int cA = (lane>>4)*8;
    int rB = wn*32 + ((lane>>4)<<3) + (lane&7);
    int cB = ((lane>>3)&1)*8;

    float au[2][4][4] = {}, avv[2][4][4] = {};

    for (int nk = 0; nk < 2; nk++) {
        int kc0 = nk * 64;
        #pragma unroll
        for (int it = 0; it < 4; it++) {
            int idx = tid + it*256;
            int r = idx >> 3, c8 = (idx & 7) << 3;
            size_t go = (size_t)(bm + r) * 128 + kc0 + c8;
            *(uint4*)&Ah[r*AST + c8] = *(const uint4*)(g_hh + go);
            *(uint4*)&Al[r*AST + c8] = *(const uint4*)(g_hl + go);
        }
        #pragma unroll
        for (int it = 0; it < 2; it++) {
            int idx = tid + it*256;
            int n = idx >> 3, c8 = (idx & 7) << 3;
            size_t go = (size_t)(bn + n) * 128 + kc0 + c8;
            *(uint4*)&B1h[n*AST + c8] = *(const uint4*)(g_w1_h + go);
            *(uint4*)&B1l[n*AST + c8] = *(const uint4*)(g_w1_l + go);
            *(uint4*)&B2h[n*AST + c8] = *(const uint4*)(g_w2_h + go);
            *(uint4*)&B2l[n*AST + c8] = *(const uint4*)(g_w2_l + go);
        }
        __syncthreads();

        #pragma unroll
        for (int kk = 0; kk < 4; kk++) {
            int kb = kk * 16;
            uint32_t afh[2][4], afl[2][4];
            uint32_t b1f[4][2], b1g[4][2], b2f[4][2], b2g[4][2];
            #pragma unroll
            for (int mt = 0; mt < 2; mt++) {
                uint32_t off = (uint32_t)(((rA + mt*16)*AST + kb + cA) * 2);
                ldsm_x4(afh[mt][0], afh[mt][1], afh[mt][2], afh[mt][3], aBaseH + off);
                ldsm_x4(afl[mt][0], afl[mt][1], afl[mt][2], afl[mt][3], aBaseL + off);
            }
            #pragma unroll
            for (int ntp = 0; ntp < 2; ntp++) {
                uint32_t off = (uint32_t)(((rB + ntp*16)*AST + kb + cB) * 2);
                ldsm_x4(b1f[2*ntp][0], b1f[2*ntp][1], b1f[2*ntp+1][0], b1f[2*ntp+1][1], b1BaseH + off);
                ldsm_x4(b1g[2*ntp][0], b1g[2*ntp][1], b1g[2*ntp+1][0], b1g[2*ntp+1][1], b1BaseL + off);
                ldsm_x4(b2f[2*ntp][0], b2f[2*ntp][1], b2f[2*ntp+1][0], b2f[2*ntp+1][1], b2BaseH + off);
                ldsm_x4(b2g[2*ntp][0], b2g[2*ntp][1], b2g[2*ntp+1][0], b2g[2*ntp+1][1], b2BaseL + off);
            }
            #pragma unroll
            for (int nt = 0; nt < 4; nt++)
                #pragma unroll
                for (int mt = 0; mt < 2; mt++) {
                    mma_bf16(au [mt][nt], afh[mt], b1f[nt]);
                    mma_bf16(au [mt][nt], afh[mt], b1g[nt]);
                    mma_bf16(au [mt][nt], afl[mt], b1f[nt]);
                    mma_bf16(avv[mt][nt], afh[mt], b2f[nt]);
                    mma_bf16(avv[mt][nt], afh[mt], b2g[nt]);
                    mma_bf16(avv[mt][nt], afl[mt], b2f[nt]);
                }
        }
        if (nk == 0) __syncthreads();
    }
    #pragma unroll
    for (int mt = 0; mt < 2; mt++)
        #pragma unroll
        for (int nt = 0; nt < 4; nt++)
            #pragma unroll
            for (int ci = 0; ci < 4; ci++) {
                int r = bm + wm * 32 + mt * 16 + gq + ((ci >> 1) ? 8 : 0);
                int c = bn + wn * 32 + nt * 8 + 2 * t4 + (ci & 1);
                float uu = au[mt][nt][ci];
                float val = (uu * d_sigmoid(uu)) * avv[mt][nt][ci];
                __nv_bfloat16 h, l;
                split2(val, h, l);
                g_uh[(size_t)r * DFF + c] = h;
                g_ul[(size_t)r * DFF + c] = l;
            }
}

// ---------------- fused prep: group ranges + token ranges + winner zero ----------------
__global__ void k_prep(const int* __restrict__ tok) {
    int idx = blockIdx.x * blockDim.x + threadIdx.x;
    if (idx < ROWS*MAXG/4)
        ((int4*)g_winc)[idx] = make_int4(-1, -1, -1, -1);
    if (idx < ROWS) {
        int b = idx / NATOM, ii = idx % NATOM;
        const int* t = tok + b * NATOM;
        int v = t[ii];
        g_gs[idx] = d_lower_bound(t, NATOM, v);
        g_ge[idx] = d_upper_bound(t, NATOM, v);
    }
    if (idx < NSEG) {
        int b = idx / NTOK, tt = idx % NTOK;
        const int* ta = tok + b * NATOM;
        int lo = d_lower_bound(ta, NATOM, tt);
        int hi = d_upper_bound(ta, NATOM, tt);
        g_ts[idx] = lo; g_tc[idx] = hi - lo;
    }
}

// ---------------- pair scatter pass 1: last-write-wins winner ----------------
__global__ void k_scatmax(const int* __restrict__ plmidx, const int* __restrict__ tok) {
    int gid = blockIdx.x * blockDim.x + threadIdx.x;
    if (gid >= BATCH * NPAIR) return;
    int b = gid / NPAIR, p = gid % NPAIR;
    int src = plmidx[(size_t)gid*2], dst = plmidx[(size_t)gid*2 + 1];
    if (tok[b*NATOM + src] != tok[b*NATOM + dst]) return;
    int i = b*NATOM + src;
    int slot = dst - g_gs[i];
    if (slot >= 0 && slot < MAXG)
        atomicMax(&g_winc[(size_t)i * MAXG + slot], p);
}

// ---------------- pass 2: slot-ordered bias fill (coalesced; zeros losers) ----------------
__global__ void k_biasfill(const float* __restrict__ p_lm,
                           const float* __restrict__ pb_w, const float* __restrict__ pb_b) {
    int slot = blockIdx.x * blockDim.x + threadIdx.x;
    if (slot >= ROWS * MAXG) return;
    int w = g_winc[slot];
    float4 v = make_float4(0.f, 0.f, 0.f, 0.f);
    if (w >= 0) {
        int i = slot / MAXG;
        int b = i / NATOM;
        const float* pl = p_lm + ((size_t)b * NPAIR + w) * 16;
        float h0 = pb_b[0], h1 = pb_b[1], h2 = pb_b[2], h3 = pb_b[3];
        #pragma unroll
        for (int k = 0; k < 16; k++) {
            float plk = pl[k];
            h0 += plk * pb_w[k*NHEAD + 0];
            h1 += plk * pb_w[k*NHEAD + 1];
            h2 += plk * pb_w[k*NHEAD + 2];
            h3 += plk * pb_w[k*NHEAD + 3];
        }
        v = make_float4(h0, h1, h2, h3);
    }
    ((float4*)g_biasc)[slot] = v;
}

// ---------------- block-diagonal attention: 1 block/atom, 1 warp/head ----------------
__global__ void k_attn() {
    int i = blockIdx.x;
    int b = i / NATOM;
    int h = threadIdx.x >> 5, lane = threadIdx.x & 31;
    int s = g_gs[i], e = g_ge[i];
    const float* qrow = g_qkvg + (size_t)i * 512;
    float qd = qrow[h*DHEAD + lane];
    const float* biasrow = g_biasc + (size_t)i * MAXG * NHEAD + h;
    float m = -1e30f, l = 0.0f, acc = 0.0f;
    for (int j = s; j < e; j++) {
        const float* row = g_qkvg + (size_t)(b*NATOM + j) * 512;
        float sc = qd * row[DATOM + h*DHEAD + lane];
        #pragma unroll
        for (int o = 16; o; o >>= 1) sc += __shfl_xor_sync(0xffffffffu, sc, o);
        int slot = j - s;
        float bias = (slot < MAXG) ? biasrow[(size_t)slot * NHEAD] : 0.0f;
        sc = sc * 0.17677669529663687f + bias;
        float mn = fmaxf(m, sc);
        float corr = __expf(m - mn);
        float w = __expf(sc - mn);
        l = l * corr + w;
        acc = acc * corr + w * row[2*DATOM + h*DHEAD + lane];
        m = mn;
    }
    __nv_bfloat16 hh, ll;
    split2(acc / l, hh, ll);
    g_ao_h[(size_t)i * DATOM + h*DHEAD + lane] = hh;
    g_ao_l[(size_t)i * DATOM + h*DHEAD + lane] = ll;
}

// ---------------- segment mean of q1 (4096x128 -> 1024x128 bf16 hi/lo) ----------------
__global__ void k_segmeanq() {
    int seg = blockIdx.x;
    int b = seg / NTOK;
    int d = threadIdx.x;
    int s = g_ts[seg], c = g_tc[seg];
    float sum = 0.0f;
    for (int k = 0; k < c; k++)
        sum += g_q1[(size_t)(b*NATOM + s + k) * DATOM + d];
    float m = c ? sum / (float)c : 0.0f;
    __nv_bfloat16 h, l;
    split2(m, h, l);
    g_mqh[(size_t)seg * DATOM + d] = h;
    g_mql[(size_t)seg * DATOM + d] = l;
}

// ---------------- launch ----------------
extern "C" void kernel_launch(void* const* d_in, const int* in_sizes, int n_in,
                              void* d_out, int out_size) {
    int shift = (in_sizes[4] == 1) ? 1 : 0;
    const float* c_atom    = (const float*)d_in[0];
    const float* p_lm      = (const float*)d_in[1];
    const int*   p_lm_idx  = (const int*)  d_in[2];
    const int*   token_idx = (const int*)  d_in[3];
    const float* ln_attn_g = (const float*)d_in[4+shift];
    const float* ln_attn_b = (const float*)d_in[5+shift];
    const float* w_q       = (const float*)d_in[6+shift];
    const float* w_k       = (const float*)d_in[7+shift];
    const float* w_v       = (const float*)d_in[8+shift];
    const float* w_g       = (const float*)d_in[9+shift];
    const float* w_o       = (const float*)d_in[10+shift];
    const float* pb_w      = (const float*)d_in[11+shift];
    const float* pb_b      = (const float*)d_in[12+shift];
    const float* ln_ff_g   = (const float*)d_in[13+shift];
    const float* ln_ff_b   = (const float*)d_in[14+shift];
    const float* sw_w1     = (const float*)d_in[15+shift];
    const float* sw_w2     = (const float*)d_in[16+shift];
    const float* sw_w3     = (const float*)d_in[17+shift];
    const float* tok_w     = (const float*)d_in[18+shift];
    const float* tok_b     = (const float*)d_in[19+shift];
    float* out = (float*)d_out;

    float *p_qkvg, *p_q1;
    cudaGetSymbolAddress((void**)&p_qkvg, g_qkvg);
    cudaGetSymbolAddress((void**)&p_q1,   g_q1);
    __nv_bfloat16 *p_qnh, *p_qnl, *p_aoh, *p_aol, *p_hh, *p_hl, *p_uh, *p_ul, *p_mqh, *p_mql;
    cudaGetSymbolAddress((void**)&p_qnh, g_qn_h);  cudaGetSymbolAddress((void**)&p_qnl, g_qn_l);
    cudaGetSymbolAddress((void**)&p_aoh, g_ao_h);  cudaGetSymbolAddress((void**)&p_aol, g_ao_l);
    cudaGetSymbolAddress((void**)&p_hh,  g_hh);    cudaGetSymbolAddress((void**)&p_hl,  g_hl);
    cudaGetSymbolAddress((void**)&p_uh,  g_uh);    cudaGetSymbolAddress((void**)&p_ul,  g_ul);
    cudaGetSymbolAddress((void**)&p_mqh, g_mqh);   cudaGetSymbolAddress((void**)&p_mql, g_mql);
    __nv_bfloat16 *p_wqh, *p_wql, *p_woh, *p_wol, *p_w1h, *p_w1l, *p_w2h, *p_w2l,
                  *p_w3h, *p_w3l, *p_twh, *p_twl;
    cudaGetSymbolAddress((void**)&p_wqh, g_wqkvg_h); cudaGetSymbolAddress((void**)&p_wql, g_wqkvg_l);
    cudaGetSymbolAddress((void**)&p_woh, g_wo_h);    cudaGetSymbolAddress((void**)&p_wol, g_wo_l);
    cudaGetSymbolAddress((void**)&p_w1h, g_w1_h);    cudaGetSymbolAddress((void**)&p_w1l, g_w1_l);
    cudaGetSymbolAddress((void**)&p_w2h, g_w2_h);    cudaGetSymbolAddress((void**)&p_w2l, g_w2_l);
    cudaGetSymbolAddress((void**)&p_w3h, g_w3_h);    cudaGetSymbolAddress((void**)&p_w3l, g_w3_l);
    cudaGetSymbolAddress((void**)&p_twh, g_tw_h);    cudaGetSymbolAddress((void**)&p_twl, g_tw_l);

    // dynamic smem opt-in (idempotent)
    const int SMQ  = 2 * AST * (128 + 64) * 2;    // 55296 B  (BM=128 kernels)
    const int SMW  = 2 * AST * ( 64 + 64) * 2;    // 36864 B  (BM=64 kernels)
    const int SMF  = 2 * AST * (128 + 128) * 2;   // 73728 B  (FFN dual-B)
    cudaFuncSetAttribute(k_mma<128,2,1>, cudaFuncAttributeMaxDynamicSharedMemorySize, SMQ);
    cudaFuncSetAttribute(k_mma<64,2,2>,  cudaFuncAttributeMaxDynamicSharedMemorySize, SMW);
    cudaFuncSetAttribute(k_mma<64,8,4>,  cudaFuncAttributeMaxDynamicSharedMemorySize, SMW);
    cudaFuncSetAttribute(k_mma<128,2,5>, cudaFuncAttributeMaxDynamicSharedMemorySize, SMQ);
    cudaFuncSetAttribute(k_mma_ffn,      cudaFuncAttributeMaxDynamicSharedMemorySize, SMF);

    // side stream (created once; identical work every call)
    static cudaStream_t s_side = nullptr;
    static cudaEvent_t  e_fork = nullptr, e_wc = nullptr, e_join = nullptr;
    if (!s_side) {
        cudaStreamCreateWithFlags(&s_side, cudaStreamNonBlocking);
        cudaEventCreateWithFlags(&e_fork, cudaEventDisableTiming);
        cudaEventCreateWithFlags(&e_wc,   cudaEventDisableTiming);
        cudaEventCreateWithFlags(&e_join, cudaEventDisableTiming);
    }

    // ---- descriptor table ----
    WAll wa;
    wa.w[0] = { w_q,   p_wqh + 0*16384, p_wql + 0*16384, 128, 128,   0 };
    wa.w[1] = { w_k,   p_wqh + 1*16384, p_wql + 1*16384, 128, 128,  16 };
    wa.w[2] = { w_v,   p_wqh + 2*16384, p_wql + 2*16384, 128, 128,  32 };
    wa.w[3] = { w_g,   p_wqh + 3*16384, p_wql + 3*16384, 128, 128,  48 };
    wa.w[4] = { w_o,   p_woh,           p_wol,           128, 128,  64 };
    wa.w[5] = { sw_w1, p_w1h,           p_w1l,           128, 512,  80 };
    wa.w[6] = { sw_w2, p_w2h,           p_w2l,           128, 512, 144 };
    wa.w[7] = { sw_w3, p_w3h,           p_w3l,           512, 128, 208 };
    wa.w[8] = { tok_w, p_twh,           p_twl,           128, 512, 272 };

    // ---- fork: ONE weight-convert launch + bias chain on side stream ----
    cudaEventRecord(e_fork, 0);
    cudaStreamWaitEvent(s_side, e_fork, 0);
    k_wconv_all<<<WC_TILES, 256, 0, s_side>>>(wa);
    cudaEventRecord(e_wc, s_side);
    k_prep    <<<ROWS*MAXG/4/256, 256, 0, s_side>>>(token_idx);
    k_scatmax <<<(BATCH*NPAIR)/256, 256, 0, s_side>>>(p_lm_idx, token_idx);
    k_biasfill<<<ROWS*MAXG/256, 256, 0, s_side>>>(p_lm, pb_w, pb_b);
    cudaEventRecord(e_join, s_side);

    // ---- main chain ----
    k_ln<<<ROWS/4, 128>>>(c_atom, ln_attn_g, ln_attn_b, p_qnh, p_qnl);
    cudaStreamWaitEvent(0, e_wc, 0);
    k_mma<128,2,1><<<dim3(8, ROWS/128), 256, SMQ>>>(
        p_qnh, p_qnl, 128, p_wqh, p_wql, 128, p_qkvg, 512, nullptr, nullptr);

    cudaStreamWaitEvent(0, e_join, 0);   // bias ready
    k_attn<<<ROWS, 128>>>();

    k_mma<64,2,2><<<dim3(2, ROWS/64), 256, SMW>>>(
        p_aoh, p_aol, 128, p_woh, p_wol, 128, nullptr, 0, c_atom, nullptr);
    k_ln<<<ROWS/4, 128>>>(p_q1, ln_ff_g, ln_ff_b, p_hh, p_hl);
    k_mma_ffn<<<dim3(DFF/64, ROWS/128), 256, SMF>>>();
    k_mma<64,8,4><<<dim3(2, ROWS/64), 256, SMW>>>(
        p_uh, p_ul, 512, p_w3h, p_w3l, 512, nullptr, 0, nullptr, nullptr);

    // segment-mean BEFORE token projection (linearity), then small GEMM -> out
    k_segmeanq<<<NSEG, DATOM>>>();
    k_mma<128,2,5><<<dim3(DMODEL/64, NSEG/128), 256, SMQ>>>(
        p_mqh, p_mql, 128, p_twh, p_twl, 128, out, DMODEL, nullptr, tok_b);
}